// round 1
// baseline (speedup 1.0000x reference)
#include <cuda_runtime.h>
#include <math.h>

// ---------------------------------------------------------------------------
// Problem constants (fixed shapes)
// ---------------------------------------------------------------------------
constexpr int Bb = 32;
constexpr int Hh = 56;
constexpr int Ww = 56;
constexpr int Cc = 128;
constexpr int Nn = Hh * Ww;          // 3136
constexpr int Mm = Bb * Nn;          // 100352 tokens
constexpr size_t MC = (size_t)Mm * Cc;   // 12,845,056 elements

// ---------------------------------------------------------------------------
// Scratch (static device globals; no allocations allowed)
// ---------------------------------------------------------------------------
__device__ float g_t0[MC];
__device__ float g_t1[MC];
__device__ float g_x1a[MC];
__device__ float g_x2a[MC];
__device__ float g_q[MC];
__device__ float g_k[MC];
__device__ float g_v[MC];
__device__ float g_att[MC];
__device__ float g_ln[MC * 2];           // [M, 256]
__device__ float g_part[784 * 256];      // BN partial sums
__device__ float g_scale[Cc];
__device__ float g_shift[Cc];
__device__ float g_wT[3 * Cc * Cc];      // q/k/v weights transposed to [Cin,Cout]

// ---------------------------------------------------------------------------
// Per-channel circular roll.  MODE 0: H,+c   MODE 1: W,+c   MODE 2: W,-c
// out[b,h,w,c] = in[b, h', w', c]
// ---------------------------------------------------------------------------
template <int MODE>
__global__ void roll_k(const float* __restrict__ in, float* __restrict__ out) {
    int idx = blockIdx.x * blockDim.x + threadIdx.x;   // < Mm*Cc
    int c = idx & 127;
    int n = idx >> 7;
    int w = n % Ww;
    int h = (n / Ww) % Hh;
    int b = n / (Hh * Ww);
    int cm = c % 56;
    int hs = h, ws = w;
    if (MODE == 0) { hs = h - cm; if (hs < 0) hs += 56; }
    else if (MODE == 1) { ws = w - cm; if (ws < 0) ws += 56; }
    else { ws = w + cm; if (ws >= 56) ws -= 56; }
    int nsrc = (b * Hh + hs) * Ww + ws;
    out[idx] = in[(size_t)nsrc * Cc + c];
}

// ---------------------------------------------------------------------------
// SGEMM: C[M,128] = A[M,K] @ B[K,128] (+ epilogue)
// BM=128, BN=128, BK=16, 256 threads, 8x8 per-thread tile.
// SPLIT=true: A columns [0,128) come from A0, [128,256) from A1 (both [M,128]).
// ---------------------------------------------------------------------------
enum { EPI_GELU = 0, EPI_BIAS = 1, EPI_RES = 2 };

template <int K, int EPI, bool SPLIT>
__launch_bounds__(256)
__global__ void gemm_k(const float* __restrict__ A0, const float* __restrict__ A1,
                       const float* __restrict__ Bm, const float* __restrict__ bias,
                       const float* __restrict__ res, float* __restrict__ Cm) {
    __shared__ float As[16][128];
    __shared__ float Bs[16][128];
    const int tid = threadIdx.x;
    const int tx = tid & 15;
    const int ty = tid >> 4;
    const int row0 = blockIdx.x * 128;
    float acc[8][8] = {};

    for (int kk0 = 0; kk0 < K; kk0 += 16) {
        // --- A tile (128 rows x 16 cols), stored transposed into As[k][m] ---
        const float* Ab;
        int lda;
        if (SPLIT) {
            lda = 128;
            Ab = (kk0 < 128) ? (A0 + (size_t)row0 * 128 + kk0)
                             : (A1 + (size_t)row0 * 128 + (kk0 - 128));
        } else {
            lda = K;
            Ab = A0 + (size_t)row0 * K + kk0;
        }
        #pragma unroll
        for (int e = tid; e < 512; e += 256) {
            int r  = e >> 2;
            int c4 = (e & 3) * 4;
            float4 va = *(const float4*)(Ab + (size_t)r * lda + c4);
            As[c4 + 0][r] = va.x;
            As[c4 + 1][r] = va.y;
            As[c4 + 2][r] = va.z;
            As[c4 + 3][r] = va.w;
        }
        // --- B tile (16 x 128) ---
        #pragma unroll
        for (int e = tid; e < 512; e += 256) {
            int r  = e >> 5;
            int c4 = (e & 31) * 4;
            *(float4*)&Bs[r][c4] = *(const float4*)(Bm + (size_t)(kk0 + r) * 128 + c4);
        }
        __syncthreads();

        #pragma unroll
        for (int kk = 0; kk < 16; kk++) {
            float a[8], bfr[8];
            *(float4*)&a[0]   = *(float4*)&As[kk][ty * 8];
            *(float4*)&a[4]   = *(float4*)&As[kk][ty * 8 + 4];
            *(float4*)&bfr[0] = *(float4*)&Bs[kk][tx * 8];
            *(float4*)&bfr[4] = *(float4*)&Bs[kk][tx * 8 + 4];
            #pragma unroll
            for (int i = 0; i < 8; i++)
                #pragma unroll
                for (int j = 0; j < 8; j++)
                    acc[i][j] += a[i] * bfr[j];
        }
        __syncthreads();
    }

    #pragma unroll
    for (int i = 0; i < 8; i++) {
        int m = row0 + ty * 8 + i;
        #pragma unroll
        for (int j = 0; j < 8; j++) {
            int n = tx * 8 + j;
            float v = acc[i][j] + bias[n];
            if (EPI == EPI_GELU) {
                v = 0.5f * v * (1.0f + erff(v * 0.70710678118654752f));
            } else if (EPI == EPI_RES) {
                v += res[(size_t)m * 128 + n];
            }
            Cm[(size_t)m * 128 + n] = v;
        }
    }
}

// ---------------------------------------------------------------------------
// LayerNorm over the 256-wide concat of x1a|x2a, one warp per token.
// ---------------------------------------------------------------------------
__global__ void ln_k(const float* __restrict__ x1a, const float* __restrict__ x2a,
                     const float* __restrict__ lw, const float* __restrict__ lb,
                     float* __restrict__ out) {
    int warp = (blockIdx.x * blockDim.x + threadIdx.x) >> 5;
    int lane = threadIdx.x & 31;
    if (warp >= Mm) return;
    float v[8];
    #pragma unroll
    for (int kq = 0; kq < 4; kq++) v[kq]     = x1a[(size_t)warp * 128 + lane + 32 * kq];
    #pragma unroll
    for (int kq = 0; kq < 4; kq++) v[4 + kq] = x2a[(size_t)warp * 128 + lane + 32 * kq];
    float s = 0.f, sq = 0.f;
    #pragma unroll
    for (int kq = 0; kq < 8; kq++) { s += v[kq]; sq += v[kq] * v[kq]; }
    #pragma unroll
    for (int o = 16; o > 0; o >>= 1) {
        s  += __shfl_xor_sync(0xffffffffu, s, o);
        sq += __shfl_xor_sync(0xffffffffu, sq, o);
    }
    float mean = s * (1.f / 256.f);
    float var  = sq * (1.f / 256.f) - mean * mean;
    float rstd = rsqrtf(var + 1e-5f);
    #pragma unroll
    for (int kq = 0; kq < 8; kq++) {
        int i = (kq < 4) ? (lane + 32 * kq) : (128 + lane + 32 * (kq - 4));
        out[(size_t)warp * 256 + i] = (v[kq] - mean) * rstd * lw[i] + lb[i];
    }
}

// ---------------------------------------------------------------------------
// Transpose q/k/v weights [Cout,Cin] -> [Cin,Cout]
// ---------------------------------------------------------------------------
__global__ void transpose_w(const float* __restrict__ qw, const float* __restrict__ kw,
                            const float* __restrict__ vw, float* __restrict__ wT) {
    int idx = blockIdx.x * blockDim.x + threadIdx.x;   // < 3*16384
    int t = idx >> 14;
    int r = idx & 16383;
    int cin = r >> 7;
    int o = r & 127;
    const float* src = (t == 0) ? qw : (t == 1) ? kw : vw;
    wT[idx] = src[o * 128 + cin];
}

// ---------------------------------------------------------------------------
// Window attention: one block per 7x7 window (2048 windows), single head C=128
// ---------------------------------------------------------------------------
__global__ void attn_k(const float* __restrict__ q, const float* __restrict__ k,
                       const float* __restrict__ v, float* __restrict__ out) {
    extern __shared__ float sm[];
    float* qs = sm;                 // 49*128
    float* ks = qs + 49 * 128;
    float* vs = ks + 49 * 128;
    __shared__ float sc[49 * 49];

    int wid = blockIdx.x;           // 0..2047
    int b  = wid >> 6;
    int wh = (wid >> 3) & 7;
    int ww = wid & 7;
    int tid = threadIdx.x;

    for (int e = tid; e < 49 * 128; e += 256) {
        int i = e >> 7, c = e & 127;
        size_t g = ((size_t)(b * Nn + (wh * 7 + i / 7) * Ww + ww * 7 + (i % 7))) * 128 + c;
        qs[e] = q[g];
        ks[e] = k[g];
        vs[e] = v[g];
    }
    __syncthreads();

    const float scale = 0.08838834764831845f;   // 128^-0.5
    for (int e = tid; e < 49 * 49; e += 256) {
        int i = e / 49, j = e % 49;
        const float* qp = qs + i * 128;
        const float* kp = ks + j * 128;
        float s = 0.f;
        #pragma unroll
        for (int c = 0; c < 128; c += 4) {
            float4 a  = *(const float4*)(qp + c);
            float4 bb = *(const float4*)(kp + c);
            s += a.x * bb.x + a.y * bb.y + a.z * bb.z + a.w * bb.w;
        }
        sc[e] = s * scale;
    }
    __syncthreads();

    if (tid < 49) {
        float* r = sc + tid * 49;
        float mx = r[0];
        #pragma unroll
        for (int j = 1; j < 49; j++) mx = fmaxf(mx, r[j]);
        float sum = 0.f;
        #pragma unroll
        for (int j = 0; j < 49; j++) { float e2 = expf(r[j] - mx); r[j] = e2; sum += e2; }
        float inv = 1.f / sum;
        #pragma unroll
        for (int j = 0; j < 49; j++) r[j] *= inv;
    }
    __syncthreads();

    for (int e = tid; e < 49 * 128; e += 256) {
        int i = e >> 7, c = e & 127;
        float s = 0.f;
        #pragma unroll 7
        for (int j = 0; j < 49; j++) s += sc[i * 49 + j] * vs[j * 128 + c];
        size_t g = ((size_t)(b * Nn + (wh * 7 + i / 7) * Ww + ww * 7 + (i % 7))) * 128 + c;
        out[g] = s;
    }
}

// ---------------------------------------------------------------------------
// BatchNorm (training-mode batch stats), deterministic two-stage reduction
// ---------------------------------------------------------------------------
__global__ void bn_stats_k(const float* __restrict__ x, float* __restrict__ part) {
    // 784 blocks x 128 rows each; 256 threads (2 row-lanes x 128 channels)
    int c = threadIdx.x & 127;
    int half = threadIdx.x >> 7;
    float s = 0.f, sq = 0.f;
    int rbeg = blockIdx.x * 128 + half;
    int rend = blockIdx.x * 128 + 128;
    for (int r = rbeg; r < rend; r += 2) {
        float vv = x[(size_t)r * 128 + c];
        s += vv; sq += vv * vv;
    }
    __shared__ float sh[512];
    sh[threadIdx.x] = s;
    sh[256 + threadIdx.x] = sq;
    __syncthreads();
    if (half == 0) {
        part[blockIdx.x * 256 + c]       = sh[c] + sh[128 + c];
        part[blockIdx.x * 256 + 128 + c] = sh[256 + c] + sh[256 + 128 + c];
    }
}

__global__ void bn_reduce_k(const float* __restrict__ part, const float* __restrict__ g,
                            const float* __restrict__ beta, float* __restrict__ scale,
                            float* __restrict__ shift) {
    int c = threadIdx.x;   // 128 threads
    float s = 0.f, sq = 0.f;
    for (int i = 0; i < 784; i++) {
        s  += part[i * 256 + c];
        sq += part[i * 256 + 128 + c];
    }
    float mean = s / (float)Mm;
    float var  = sq / (float)Mm - mean * mean;
    float sc_  = g[c] * rsqrtf(var + 1e-5f);
    scale[c] = sc_;
    shift[c] = beta[c] - mean * sc_;
}

template <bool RELU>
__global__ void bn_apply_k(float* __restrict__ x, const float* __restrict__ scale,
                           const float* __restrict__ shift) {
    int idx = blockIdx.x * blockDim.x + threadIdx.x;
    int c = idx & 127;
    float v = x[idx] * scale[c] + shift[c];
    if (RELU) v = fmaxf(v, 0.f);
    x[idx] = v;
}

// ---------------------------------------------------------------------------
// Host launch
// ---------------------------------------------------------------------------
static float* symaddr(const void* devsym) {
    void* p = nullptr;
    cudaGetSymbolAddress(&p, devsym);
    return (float*)p;
}

extern "C" void kernel_launch(void* const* d_in, const int* in_sizes, int n_in,
                              void* d_out, int out_size) {
    const float* x     = (const float*)d_in[0];
    const float* fc1_w = (const float*)d_in[1];
    const float* fc1_b = (const float*)d_in[2];
    const float* fc2_w = (const float*)d_in[3];
    const float* fc2_b = (const float*)d_in[4];
    const float* fc3_w = (const float*)d_in[5];
    const float* fc3_b = (const float*)d_in[6];
    const float* fc4_w = (const float*)d_in[7];
    const float* fc4_b = (const float*)d_in[8];
    const float* fc5_w = (const float*)d_in[9];
    const float* fc5_b = (const float*)d_in[10];
    const float* fc6_w = (const float*)d_in[11];
    const float* fc6_b = (const float*)d_in[12];
    const float* ln_w  = (const float*)d_in[13];
    const float* ln_b  = (const float*)d_in[14];
    const float* q_w   = (const float*)d_in[15];
    const float* q_b   = (const float*)d_in[16];
    const float* k_w   = (const float*)d_in[17];
    const float* k_b   = (const float*)d_in[18];
    const float* v_w   = (const float*)d_in[19];
    const float* v_b   = (const float*)d_in[20];
    const float* bn1_g = (const float*)d_in[21];
    const float* bn1_b = (const float*)d_in[22];
    const float* bn2_g = (const float*)d_in[23];
    const float* bn2_b = (const float*)d_in[24];

    float* t0   = symaddr(g_t0);
    float* t1   = symaddr(g_t1);
    float* x1a  = symaddr(g_x1a);
    float* x2a  = symaddr(g_x2a);
    float* qb   = symaddr(g_q);
    float* kb   = symaddr(g_k);
    float* vb   = symaddr(g_v);
    float* att  = symaddr(g_att);
    float* lnb  = symaddr(g_ln);
    float* part = symaddr(g_part);
    float* scl  = symaddr(g_scale);
    float* shf  = symaddr(g_shift);
    float* wT   = symaddr(g_wT);

    const int gridE = (int)(MC / 256);   // 50176
    const int gridG = Mm / 128;          // 784

    // Branch 1: roll H(+c) -> fc1+GELU -> roll W(+c) -> fc2 + x
    roll_k<0><<<gridE, 256>>>(x, t0);
    gemm_k<128, EPI_GELU, false><<<gridG, 256>>>(t0, nullptr, fc1_w, fc1_b, nullptr, t1);
    roll_k<1><<<gridE, 256>>>(t1, t0);
    gemm_k<128, EPI_RES, false><<<gridG, 256>>>(t0, nullptr, fc2_w, fc2_b, x, x1a);

    // Branch 2: roll W(-c) -> fc3+GELU -> roll H(+c) -> fc4 + x
    roll_k<2><<<gridE, 256>>>(x, t0);
    gemm_k<128, EPI_GELU, false><<<gridG, 256>>>(t0, nullptr, fc3_w, fc3_b, nullptr, t1);
    roll_k<0><<<gridE, 256>>>(t1, t0);
    gemm_k<128, EPI_RES, false><<<gridG, 256>>>(t0, nullptr, fc4_w, fc4_b, x, x2a);

    // LN over concat, fc5 + x  -> t0 = x1 (final)
    ln_k<<<Mm / 8, 256>>>(x1a, x2a, ln_w, ln_b, lnb);
    gemm_k<256, EPI_RES, false><<<gridG, 256>>>(lnb, nullptr, fc5_w, fc5_b, x, t0);

    // q/k/v projections (conv weights are [Cout,Cin]; transpose first)
    transpose_w<<<(3 * Cc * Cc) / 256, 256>>>(q_w, k_w, v_w, wT);
    gemm_k<128, EPI_BIAS, false><<<gridG, 256>>>(x, nullptr, wT,             q_b, nullptr, qb);
    gemm_k<128, EPI_BIAS, false><<<gridG, 256>>>(x, nullptr, wT + Cc * Cc,   k_b, nullptr, kb);
    gemm_k<128, EPI_BIAS, false><<<gridG, 256>>>(x, nullptr, wT + 2 * Cc*Cc, v_b, nullptr, vb);

    // Window attention
    cudaFuncSetAttribute(attn_k, cudaFuncAttributeMaxDynamicSharedMemorySize, 3 * 49 * 128 * 4);
    attn_k<<<2048, 256, 3 * 49 * 128 * 4>>>(qb, kb, vb, att);

    // BN1 + ReLU (in place), then BN2 (in place)
    bn_stats_k<<<784, 256>>>(att, part);
    bn_reduce_k<<<1, 128>>>(part, bn1_g, bn1_b, scl, shf);
    bn_apply_k<true><<<gridE, 256>>>(att, scl, shf);
    bn_stats_k<<<784, 256>>>(att, part);
    bn_reduce_k<<<1, 128>>>(part, bn2_g, bn2_b, scl, shf);
    bn_apply_k<false><<<gridE, 256>>>(att, scl, shf);

    // Final: out = [x1 | x2] @ fc6_w + fc6_b
    gemm_k<256, EPI_BIAS, true><<<gridG, 256>>>(t0, att, fc6_w, fc6_b, nullptr, (float*)d_out);
}

// round 2
// speedup vs baseline: 1.3703x; 1.3703x over previous
#include <cuda_runtime.h>
#include <math.h>
#include <stdint.h>

// ---------------------------------------------------------------------------
// Problem constants
// ---------------------------------------------------------------------------
constexpr int Bb = 32;
constexpr int Hh = 56;
constexpr int Ww = 56;
constexpr int Cc = 128;
constexpr int Nn = Hh * Ww;              // 3136
constexpr int Mm = Bb * Nn;              // 100352
constexpr size_t MC = (size_t)Mm * Cc;   // 12,845,056

// ---------------------------------------------------------------------------
// Scratch
// ---------------------------------------------------------------------------
__device__ float g_t0[MC];
__device__ float g_t1[MC];
__device__ float g_x1a[MC];
__device__ float g_x2a[MC];
__device__ float g_q[MC];
__device__ float g_k[MC];
__device__ float g_v[MC];
__device__ float g_att[MC];
__device__ float g_ln[MC * 2];
__device__ float g_part[784 * 256];
__device__ float g_scale[Cc];
__device__ float g_shift[Cc];

// ---------------------------------------------------------------------------
// TF32 helpers
// ---------------------------------------------------------------------------
__device__ __forceinline__ float tf32r(float x) {
    uint32_t u;
    asm("cvt.rna.tf32.f32 %0, %1;" : "=r"(u) : "f"(x));
    return __uint_as_float(u);
}

__device__ __forceinline__ void mma_tf32(float* c, const float4& a, const float2& b) {
    asm volatile(
        "mma.sync.aligned.m16n8k8.row.col.f32.tf32.tf32.f32 "
        "{%0,%1,%2,%3}, {%4,%5,%6,%7}, {%8,%9}, {%0,%1,%2,%3};"
        : "+f"(c[0]), "+f"(c[1]), "+f"(c[2]), "+f"(c[3])
        : "r"(__float_as_uint(a.x)), "r"(__float_as_uint(a.y)),
          "r"(__float_as_uint(a.z)), "r"(__float_as_uint(a.w)),
          "r"(__float_as_uint(b.x)), "r"(__float_as_uint(b.y)));
}

// ---------------------------------------------------------------------------
// Per-channel circular roll, smem-tiled (coalesced both sides).
// MODE 0: H,+c   MODE 1: W,+c   MODE 2: W,-c
// ---------------------------------------------------------------------------
template <int MODE>
__launch_bounds__(256)
__global__ void roll_k(const float* __restrict__ in, float* __restrict__ out) {
    __shared__ float tile[56 * 128];
    const int tid = threadIdx.x;
    const int b = blockIdx.x / 56;
    const int f = blockIdx.x % 56;          // fixed w (MODE0) or fixed h (MODE1/2)
    const size_t base   = (MODE == 0) ? ((size_t)b * Nn + f) * 128
                                      : ((size_t)(b * 56 + f) * 56) * 128;
    const int    stride = (MODE == 0) ? 56 * 128 : 128;

    #pragma unroll
    for (int e = tid; e < 56 * 32; e += 256) {
        int rowi = e >> 5, c4 = e & 31;
        ((float4*)tile)[rowi * 32 + c4] =
            *(const float4*)(in + base + (size_t)rowi * stride + c4 * 4);
    }
    __syncthreads();

    #pragma unroll
    for (int e = tid; e < 56 * 128; e += 256) {
        int pos = e >> 7, c = e & 127;
        int cm = c % 56;
        int src = (MODE == 2) ? pos + cm : pos - cm;
        if (src < 0) src += 56;
        if (src >= 56) src -= 56;
        out[base + (size_t)pos * stride + c] = tile[src * 128 + c];
    }
}

// ---------------------------------------------------------------------------
// TF32 tensor-core GEMM: C[M,128] = A[M,K] @ B[K,128] (+ epilogue)
// Block tile 128x128, 8 warps (4m x 2n), warp tile 32x64, mma m16n8k8.
// Smem tiles stored in FRAGMENT ORDER -> conflict-free LDS.128/LDS.64.
// SPLIT: A cols [0,128) from A0, [128,256) from A1.
// BT:    B given as [N,K] row-major (used for q/k/v conv weights).
// FOLD:  apply per-k affine (BN) to A1 during load (SPLIT only).
// ---------------------------------------------------------------------------
enum { EPI_GELU = 0, EPI_BIAS = 1, EPI_RES = 2 };

template <int K, int EPI, bool SPLIT, bool BT, bool FOLD>
__launch_bounds__(256, 2)
__global__ void gemm_k(const float* __restrict__ A0, const float* __restrict__ A1,
                       const float* __restrict__ Bm, const float* __restrict__ bias,
                       const float* __restrict__ res,
                       const float* __restrict__ bscl, const float* __restrict__ bshf,
                       float* __restrict__ Cm) {
    __shared__ float4 As[4][8][32];    // [k8][mtile][lane] -> 4 A regs
    __shared__ float2 Bs[4][16][32];   // [k8][ntile][lane] -> 2 B regs

    const int tid  = threadIdx.x;
    const int lane = tid & 31;
    const int wid  = tid >> 5;
    const int wm   = wid & 3;          // warp row (32 rows each)
    const int wn   = wid >> 2;         // warp col (64 cols each)
    const int row0 = blockIdx.x * 128;

    float c[2][8][4] = {};

    for (int kc = 0; kc < K; kc += 32) {
        // ---- A tile load: 128 rows x 32 k, scatter into fragment order ----
        const float* Ab;
        int lda;
        if (SPLIT) {
            lda = 128;
            Ab = (kc < 128) ? (A0 + (size_t)row0 * 128 + kc)
                            : (A1 + (size_t)row0 * 128 + (kc - 128));
        } else {
            lda = K;
            Ab = A0 + (size_t)row0 * K + kc;
        }
        #pragma unroll
        for (int i = 0; i < 4; i++) {
            int e  = tid + i * 256;        // 0..1023
            int m  = e >> 3;
            int k4 = e & 7;
            float4 v = *(const float4*)(Ab + (size_t)m * lda + k4 * 4);
            if (FOLD && SPLIT && kc >= 128) {
                int kk = (kc - 128) + k4 * 4;
                v.x = v.x * bscl[kk + 0] + bshf[kk + 0];
                v.y = v.y * bscl[kk + 1] + bshf[kk + 1];
                v.z = v.z * bscl[kk + 2] + bshf[kk + 2];
                v.w = v.w * bscl[kk + 3] + bshf[kk + 3];
            }
            int mt = m >> 4, r16 = m & 15, r8 = r16 & 7, rh = r16 >> 3;
            int k8 = k4 >> 1, kh = k4 & 1;
            float* dst = (float*)As + (((k8 * 8 + mt) * 32) + r8 * 4) * 4 + (rh + 2 * kh);
            dst[0]  = tf32r(v.x);
            dst[4]  = tf32r(v.y);
            dst[8]  = tf32r(v.z);
            dst[12] = tf32r(v.w);
        }
        // ---- B tile load ----
        #pragma unroll
        for (int i = 0; i < 4; i++) {
            int e = tid + i * 256;         // 0..1023
            if (BT) {
                int n = e >> 3, k4 = e & 7;
                float4 v = *(const float4*)(Bm + (size_t)n * 128 + kc + k4 * 4);
                int k8 = k4 >> 1, reg = k4 & 1, nt = n >> 3;
                float* bs = (float*)Bs + (((k8 * 16 + nt) * 32) + (n & 7) * 4) * 2 + reg;
                bs[0] = tf32r(v.x);
                bs[2] = tf32r(v.y);
                bs[4] = tf32r(v.z);
                bs[6] = tf32r(v.w);
            } else {
                int k = e >> 5, n4 = e & 31;
                float4 v = *(const float4*)(Bm + (size_t)(kc + k) * 128 + n4 * 4);
                int k8 = k >> 3, kl = k & 7, rw = kl & 3, reg = kl >> 2;
                int nt = n4 >> 1;
                float* bs = (float*)Bs + (((k8 * 16 + nt) * 32) + (n4 & 1) * 16 + rw) * 2 + reg;
                bs[0]  = tf32r(v.x);
                bs[8]  = tf32r(v.y);
                bs[16] = tf32r(v.z);
                bs[24] = tf32r(v.w);
            }
        }
        __syncthreads();

        #pragma unroll
        for (int k8 = 0; k8 < 4; k8++) {
            float4 a0 = As[k8][wm * 2 + 0][lane];
            float4 a1 = As[k8][wm * 2 + 1][lane];
            float2 b[8];
            #pragma unroll
            for (int u = 0; u < 8; u++) b[u] = Bs[k8][wn * 8 + u][lane];
            #pragma unroll
            for (int u = 0; u < 8; u++) {
                mma_tf32(c[0][u], a0, b[u]);
                mma_tf32(c[1][u], a1, b[u]);
            }
        }
        __syncthreads();
    }

    // ---- Epilogue ----
    const int lr = lane >> 2;
    const int lc = (lane & 3) * 2;
    #pragma unroll
    for (int t = 0; t < 2; t++) {
        int m0 = row0 + wm * 32 + t * 16 + lr;
        #pragma unroll
        for (int u = 0; u < 8; u++) {
            int n = wn * 64 + u * 8 + lc;
            float b0 = bias[n], b1 = bias[n + 1];
            float v0 = c[t][u][0] + b0;
            float v1 = c[t][u][1] + b1;
            float v2 = c[t][u][2] + b0;
            float v3 = c[t][u][3] + b1;
            if (EPI == EPI_GELU) {
                v0 = 0.5f * v0 * (1.0f + erff(v0 * 0.70710678f));
                v1 = 0.5f * v1 * (1.0f + erff(v1 * 0.70710678f));
                v2 = 0.5f * v2 * (1.0f + erff(v2 * 0.70710678f));
                v3 = 0.5f * v3 * (1.0f + erff(v3 * 0.70710678f));
            } else if (EPI == EPI_RES) {
                float2 r0 = *(const float2*)(res + (size_t)m0 * 128 + n);
                float2 r1 = *(const float2*)(res + (size_t)(m0 + 8) * 128 + n);
                v0 += r0.x; v1 += r0.y; v2 += r1.x; v3 += r1.y;
            }
            *(float2*)(Cm + (size_t)m0 * 128 + n)       = make_float2(v0, v1);
            *(float2*)(Cm + (size_t)(m0 + 8) * 128 + n) = make_float2(v2, v3);
        }
    }
}

// ---------------------------------------------------------------------------
// LayerNorm over 256-wide concat, one warp per token
// ---------------------------------------------------------------------------
__global__ void ln_k(const float* __restrict__ x1a, const float* __restrict__ x2a,
                     const float* __restrict__ lw, const float* __restrict__ lb,
                     float* __restrict__ out) {
    int warp = (blockIdx.x * blockDim.x + threadIdx.x) >> 5;
    int lane = threadIdx.x & 31;
    if (warp >= Mm) return;
    float v[8];
    #pragma unroll
    for (int kq = 0; kq < 4; kq++) v[kq]     = x1a[(size_t)warp * 128 + lane + 32 * kq];
    #pragma unroll
    for (int kq = 0; kq < 4; kq++) v[4 + kq] = x2a[(size_t)warp * 128 + lane + 32 * kq];
    float s = 0.f, sq = 0.f;
    #pragma unroll
    for (int kq = 0; kq < 8; kq++) { s += v[kq]; sq += v[kq] * v[kq]; }
    #pragma unroll
    for (int o = 16; o > 0; o >>= 1) {
        s  += __shfl_xor_sync(0xffffffffu, s, o);
        sq += __shfl_xor_sync(0xffffffffu, sq, o);
    }
    float mean = s * (1.f / 256.f);
    float var  = sq * (1.f / 256.f) - mean * mean;
    float rstd = rsqrtf(var + 1e-5f);
    #pragma unroll
    for (int kq = 0; kq < 8; kq++) {
        int i = (kq < 4) ? (lane + 32 * kq) : (128 + lane + 32 * (kq - 4));
        out[(size_t)warp * 256 + i] = (v[kq] - mean) * rstd * lw[i] + lb[i];
    }
}

// ---------------------------------------------------------------------------
// Window attention (SIMT fp32), one block per 7x7 window
// ---------------------------------------------------------------------------
__global__ void attn_k(const float* __restrict__ q, const float* __restrict__ k,
                       const float* __restrict__ v, float* __restrict__ out) {
    extern __shared__ float sm[];
    float* qs = sm;
    float* ks = qs + 49 * 128;
    float* vs = ks + 49 * 128;
    __shared__ float sc[49 * 49];

    int wid = blockIdx.x;
    int b  = wid >> 6;
    int wh = (wid >> 3) & 7;
    int ww = wid & 7;
    int tid = threadIdx.x;

    for (int e = tid; e < 49 * 128; e += 256) {
        int i = e >> 7, c = e & 127;
        size_t g = ((size_t)(b * Nn + (wh * 7 + i / 7) * Ww + ww * 7 + (i % 7))) * 128 + c;
        qs[e] = q[g];
        ks[e] = k[g];
        vs[e] = v[g];
    }
    __syncthreads();

    const float scale = 0.08838834764831845f;
    for (int e = tid; e < 49 * 49; e += 256) {
        int i = e / 49, j = e % 49;
        const float* qp = qs + i * 128;
        const float* kp = ks + j * 128;
        float s = 0.f;
        #pragma unroll
        for (int c2 = 0; c2 < 128; c2 += 4) {
            float4 a  = *(const float4*)(qp + c2);
            float4 bb = *(const float4*)(kp + c2);
            s += a.x * bb.x + a.y * bb.y + a.z * bb.z + a.w * bb.w;
        }
        sc[e] = s * scale;
    }
    __syncthreads();

    if (tid < 49) {
        float* r = sc + tid * 49;
        float mx = r[0];
        #pragma unroll
        for (int j = 1; j < 49; j++) mx = fmaxf(mx, r[j]);
        float sum = 0.f;
        #pragma unroll
        for (int j = 0; j < 49; j++) { float e2 = expf(r[j] - mx); r[j] = e2; sum += e2; }
        float inv = 1.f / sum;
        #pragma unroll
        for (int j = 0; j < 49; j++) r[j] *= inv;
    }
    __syncthreads();

    for (int e = tid; e < 49 * 128; e += 256) {
        int i = e >> 7, c = e & 127;
        float s = 0.f;
        #pragma unroll 7
        for (int j = 0; j < 49; j++) s += sc[i * 49 + j] * vs[j * 128 + c];
        size_t g = ((size_t)(b * Nn + (wh * 7 + i / 7) * Ww + ww * 7 + (i % 7))) * 128 + c;
        out[g] = s;
    }
}

// ---------------------------------------------------------------------------
// BatchNorm pieces (deterministic two-stage reductions)
// ---------------------------------------------------------------------------
__global__ void bn_stats_k(const float* __restrict__ x, float* __restrict__ part) {
    int c = threadIdx.x & 127;
    int half = threadIdx.x >> 7;
    float s = 0.f, sq = 0.f;
    int rbeg = blockIdx.x * 128 + half;
    int rend = blockIdx.x * 128 + 128;
    for (int r = rbeg; r < rend; r += 2) {
        float vv = x[(size_t)r * 128 + c];
        s += vv; sq += vv * vv;
    }
    __shared__ float sh[512];
    sh[threadIdx.x] = s;
    sh[256 + threadIdx.x] = sq;
    __syncthreads();
    if (half == 0) {
        part[blockIdx.x * 256 + c]       = sh[c] + sh[128 + c];
        part[blockIdx.x * 256 + 128 + c] = sh[256 + c] + sh[256 + 128 + c];
    }
}

// apply BN1 affine + ReLU in place AND produce BN2 partial sums
__global__ void bn_apply_relu_stats_k(float* __restrict__ x,
                                      const float* __restrict__ scale,
                                      const float* __restrict__ shift,
                                      float* __restrict__ part) {
    int c = threadIdx.x & 127;
    int half = threadIdx.x >> 7;
    float sc = scale[c], sh_ = shift[c];
    float s = 0.f, sq = 0.f;
    int rbeg = blockIdx.x * 128 + half;
    int rend = blockIdx.x * 128 + 128;
    for (int r = rbeg; r < rend; r += 2) {
        float vv = fmaxf(x[(size_t)r * 128 + c] * sc + sh_, 0.f);
        x[(size_t)r * 128 + c] = vv;
        s += vv; sq += vv * vv;
    }
    __shared__ float shm[512];
    shm[threadIdx.x] = s;
    shm[256 + threadIdx.x] = sq;
    __syncthreads();
    if (half == 0) {
        part[blockIdx.x * 256 + c]       = shm[c] + shm[128 + c];
        part[blockIdx.x * 256 + 128 + c] = shm[256 + c] + shm[256 + 128 + c];
    }
}

__global__ void bn_reduce_k(const float* __restrict__ part, const float* __restrict__ g,
                            const float* __restrict__ beta, float* __restrict__ scale,
                            float* __restrict__ shift) {
    int c = threadIdx.x;
    float s = 0.f, sq = 0.f;
    for (int i = 0; i < 784; i++) {
        s  += part[i * 256 + c];
        sq += part[i * 256 + 128 + c];
    }
    float mean = s / (float)Mm;
    float var  = sq / (float)Mm - mean * mean;
    float sc_  = g[c] * rsqrtf(var + 1e-5f);
    scale[c] = sc_;
    shift[c] = beta[c] - mean * sc_;
}

// ---------------------------------------------------------------------------
// Host launch
// ---------------------------------------------------------------------------
static float* symaddr(const void* devsym) {
    void* p = nullptr;
    cudaGetSymbolAddress(&p, devsym);
    return (float*)p;
}

extern "C" void kernel_launch(void* const* d_in, const int* in_sizes, int n_in,
                              void* d_out, int out_size) {
    const float* x     = (const float*)d_in[0];
    const float* fc1_w = (const float*)d_in[1];
    const float* fc1_b = (const float*)d_in[2];
    const float* fc2_w = (const float*)d_in[3];
    const float* fc2_b = (const float*)d_in[4];
    const float* fc3_w = (const float*)d_in[5];
    const float* fc3_b = (const float*)d_in[6];
    const float* fc4_w = (const float*)d_in[7];
    const float* fc4_b = (const float*)d_in[8];
    const float* fc5_w = (const float*)d_in[9];
    const float* fc5_b = (const float*)d_in[10];
    const float* fc6_w = (const float*)d_in[11];
    const float* fc6_b = (const float*)d_in[12];
    const float* ln_w  = (const float*)d_in[13];
    const float* ln_b  = (const float*)d_in[14];
    const float* q_w   = (const float*)d_in[15];
    const float* q_b   = (const float*)d_in[16];
    const float* k_w   = (const float*)d_in[17];
    const float* k_b   = (const float*)d_in[18];
    const float* v_w   = (const float*)d_in[19];
    const float* v_b   = (const float*)d_in[20];
    const float* bn1_g = (const float*)d_in[21];
    const float* bn1_b = (const float*)d_in[22];
    const float* bn2_g = (const float*)d_in[23];
    const float* bn2_b = (const float*)d_in[24];

    float* t0   = symaddr(g_t0);
    float* t1   = symaddr(g_t1);
    float* x1a  = symaddr(g_x1a);
    float* x2a  = symaddr(g_x2a);
    float* qb   = symaddr(g_q);
    float* kb   = symaddr(g_k);
    float* vb   = symaddr(g_v);
    float* att  = symaddr(g_att);
    float* lnb  = symaddr(g_ln);
    float* part = symaddr(g_part);
    float* scl  = symaddr(g_scale);
    float* shf  = symaddr(g_shift);

    const int gridR = Bb * 56;   // 1792 roll blocks
    const int gridG = Mm / 128;  // 784

    // Branch 1
    roll_k<0><<<gridR, 256>>>(x, t0);
    gemm_k<128, EPI_GELU, false, false, false><<<gridG, 256>>>(t0, nullptr, fc1_w, fc1_b, nullptr, nullptr, nullptr, t1);
    roll_k<1><<<gridR, 256>>>(t1, t0);
    gemm_k<128, EPI_RES, false, false, false><<<gridG, 256>>>(t0, nullptr, fc2_w, fc2_b, x, nullptr, nullptr, x1a);

    // Branch 2
    roll_k<2><<<gridR, 256>>>(x, t0);
    gemm_k<128, EPI_GELU, false, false, false><<<gridG, 256>>>(t0, nullptr, fc3_w, fc3_b, nullptr, nullptr, nullptr, t1);
    roll_k<0><<<gridR, 256>>>(t1, t0);
    gemm_k<128, EPI_RES, false, false, false><<<gridG, 256>>>(t0, nullptr, fc4_w, fc4_b, x, nullptr, nullptr, x2a);

    // LN + fc5 + residual -> t0 = x1 final
    ln_k<<<Mm / 8, 256>>>(x1a, x2a, ln_w, ln_b, lnb);
    gemm_k<256, EPI_RES, false, false, false><<<gridG, 256>>>(lnb, nullptr, fc5_w, fc5_b, x, nullptr, nullptr, t0);

    // q/k/v projections (weights are [Cout,Cin] -> BT layout)
    gemm_k<128, EPI_BIAS, false, true, false><<<gridG, 256>>>(x, nullptr, q_w, q_b, nullptr, nullptr, nullptr, qb);
    gemm_k<128, EPI_BIAS, false, true, false><<<gridG, 256>>>(x, nullptr, k_w, k_b, nullptr, nullptr, nullptr, kb);
    gemm_k<128, EPI_BIAS, false, true, false><<<gridG, 256>>>(x, nullptr, v_w, v_b, nullptr, nullptr, nullptr, vb);

    // Window attention
    cudaFuncSetAttribute(attn_k, cudaFuncAttributeMaxDynamicSharedMemorySize, 3 * 49 * 128 * 4);
    attn_k<<<2048, 256, 3 * 49 * 128 * 4>>>(qb, kb, vb, att);

    // BN1 stats -> (apply BN1+ReLU, BN2 stats) -> BN2 affine folded into fc6
    bn_stats_k<<<784, 256>>>(att, part);
    bn_reduce_k<<<1, 128>>>(part, bn1_g, bn1_b, scl, shf);
    bn_apply_relu_stats_k<<<784, 256>>>(att, scl, shf, part);
    bn_reduce_k<<<1, 128>>>(part, bn2_g, bn2_b, scl, shf);

    // Final: out = [x1 | BN2(att)] @ fc6 + b
    gemm_k<256, EPI_BIAS, true, false, true><<<gridG, 256>>>(t0, att, fc6_w, fc6_b, nullptr, scl, shf, (float*)d_out);
}

// round 3
// speedup vs baseline: 1.3710x; 1.0006x over previous
#include <cuda_runtime.h>
#include <math.h>
#include <stdint.h>

// ---------------------------------------------------------------------------
// Problem constants
// ---------------------------------------------------------------------------
constexpr int Bb = 32;
constexpr int Hh = 56;
constexpr int Ww = 56;
constexpr int Cc = 128;
constexpr int Nn = Hh * Ww;              // 3136
constexpr int Mm = Bb * Nn;              // 100352
constexpr size_t MC = (size_t)Mm * Cc;   // 12,845,056

// ---------------------------------------------------------------------------
// Scratch
// ---------------------------------------------------------------------------
__device__ float g_t0[MC];
__device__ float g_t1[MC];
__device__ float g_x1a[MC];
__device__ float g_x2a[MC];
__device__ float g_q[MC];
__device__ float g_k[MC];
__device__ float g_v[MC];
__device__ float g_att[MC];
__device__ float g_ln[MC * 2];
__device__ float g_part[784 * 256];
__device__ float g_scale[Cc];
__device__ float g_shift[Cc];

// ---------------------------------------------------------------------------
// TF32 helpers
// ---------------------------------------------------------------------------
__device__ __forceinline__ float tf32r(float x) {
    uint32_t u;
    asm("cvt.rna.tf32.f32 %0, %1;" : "=r"(u) : "f"(x));
    return __uint_as_float(u);
}

__device__ __forceinline__ void mma_tf32(float* c, const float4& a, const float2& b) {
    asm volatile(
        "mma.sync.aligned.m16n8k8.row.col.f32.tf32.tf32.f32 "
        "{%0,%1,%2,%3}, {%4,%5,%6,%7}, {%8,%9}, {%0,%1,%2,%3};"
        : "+f"(c[0]), "+f"(c[1]), "+f"(c[2]), "+f"(c[3])
        : "r"(__float_as_uint(a.x)), "r"(__float_as_uint(a.y)),
          "r"(__float_as_uint(a.z)), "r"(__float_as_uint(a.w)),
          "r"(__float_as_uint(b.x)), "r"(__float_as_uint(b.y)));
}

// ---------------------------------------------------------------------------
// Per-channel circular roll, smem-tiled (coalesced both sides).
// MODE 0: H,+c   MODE 1: W,+c   MODE 2: W,-c
// ---------------------------------------------------------------------------
template <int MODE>
__launch_bounds__(256)
__global__ void roll_k(const float* __restrict__ in, float* __restrict__ out) {
    __shared__ float tile[56 * 128];
    const int tid = threadIdx.x;
    const int b = blockIdx.x / 56;
    const int f = blockIdx.x % 56;          // fixed w (MODE0) or fixed h (MODE1/2)
    const size_t base   = (MODE == 0) ? ((size_t)b * Nn + f) * 128
                                      : ((size_t)(b * 56 + f) * 56) * 128;
    const int    stride = (MODE == 0) ? 56 * 128 : 128;

    #pragma unroll
    for (int e = tid; e < 56 * 32; e += 256) {
        int rowi = e >> 5, c4 = e & 31;
        ((float4*)tile)[rowi * 32 + c4] =
            *(const float4*)(in + base + (size_t)rowi * stride + c4 * 4);
    }
    __syncthreads();

    #pragma unroll
    for (int e = tid; e < 56 * 128; e += 256) {
        int pos = e >> 7, c = e & 127;
        int cm = c % 56;
        int src = (MODE == 2) ? pos + cm : pos - cm;
        if (src < 0) src += 56;
        if (src >= 56) src -= 56;
        out[base + (size_t)pos * stride + c] = tile[src * 128 + c];
    }
}

// ---------------------------------------------------------------------------
// TF32 tensor-core GEMM: C[M,128] = A[M,K] @ B[K,128] (+ epilogue)
// Block tile 128x128, 8 warps (4m x 2n), warp tile 32x64, mma m16n8k8.
// Smem tiles stored in FRAGMENT ORDER -> conflict-free LDS.128/LDS.64.
// SPLIT: A cols [0,128) from A0, [128,256) from A1.
// BT:    B given as [N,K] row-major (used for q/k/v conv weights).
// FOLD:  apply per-k affine (BN) to A1 during load (SPLIT only).
// ---------------------------------------------------------------------------
enum { EPI_GELU = 0, EPI_BIAS = 1, EPI_RES = 2 };

template <int K, int EPI, bool SPLIT, bool BT, bool FOLD>
__launch_bounds__(256, 2)
__global__ void gemm_k(const float* __restrict__ A0, const float* __restrict__ A1,
                       const float* __restrict__ Bm, const float* __restrict__ bias,
                       const float* __restrict__ res,
                       const float* __restrict__ bscl, const float* __restrict__ bshf,
                       float* __restrict__ Cm) {
    __shared__ float4 As[4][8][32];    // [k8][mtile][lane] -> 4 A regs
    __shared__ float2 Bs[4][16][32];   // [k8][ntile][lane] -> 2 B regs

    const int tid  = threadIdx.x;
    const int lane = tid & 31;
    const int wid  = tid >> 5;
    const int wm   = wid & 3;          // warp row (32 rows each)
    const int wn   = wid >> 2;         // warp col (64 cols each)
    const int row0 = blockIdx.x * 128;

    float c[2][8][4] = {};

    for (int kc = 0; kc < K; kc += 32) {
        // ---- A tile load: 128 rows x 32 k, scatter into fragment order ----
        const float* Ab;
        int lda;
        if (SPLIT) {
            lda = 128;
            Ab = (kc < 128) ? (A0 + (size_t)row0 * 128 + kc)
                            : (A1 + (size_t)row0 * 128 + (kc - 128));
        } else {
            lda = K;
            Ab = A0 + (size_t)row0 * K + kc;
        }
        #pragma unroll
        for (int i = 0; i < 4; i++) {
            int e  = tid + i * 256;        // 0..1023
            int m  = e >> 3;
            int k4 = e & 7;
            float4 v = *(const float4*)(Ab + (size_t)m * lda + k4 * 4);
            if (FOLD && SPLIT && kc >= 128) {
                int kk = (kc - 128) + k4 * 4;
                v.x = v.x * bscl[kk + 0] + bshf[kk + 0];
                v.y = v.y * bscl[kk + 1] + bshf[kk + 1];
                v.z = v.z * bscl[kk + 2] + bshf[kk + 2];
                v.w = v.w * bscl[kk + 3] + bshf[kk + 3];
            }
            int mt = m >> 4, r16 = m & 15, r8 = r16 & 7, rh = r16 >> 3;
            int k8 = k4 >> 1, kh = k4 & 1;
            float* dst = (float*)As + (((k8 * 8 + mt) * 32) + r8 * 4) * 4 + (rh + 2 * kh);
            dst[0]  = tf32r(v.x);
            dst[4]  = tf32r(v.y);
            dst[8]  = tf32r(v.z);
            dst[12] = tf32r(v.w);
        }
        // ---- B tile load ----
        #pragma unroll
        for (int i = 0; i < 4; i++) {
            int e = tid + i * 256;         // 0..1023
            if (BT) {
                int n = e >> 3, k4 = e & 7;
                float4 v = *(const float4*)(Bm + (size_t)n * 128 + kc + k4 * 4);
                int k8 = k4 >> 1, reg = k4 & 1, nt = n >> 3;
                float* bs = (float*)Bs + (((k8 * 16 + nt) * 32) + (n & 7) * 4) * 2 + reg;
                bs[0] = tf32r(v.x);
                bs[2] = tf32r(v.y);
                bs[4] = tf32r(v.z);
                bs[6] = tf32r(v.w);
            } else {
                int k = e >> 5, n4 = e & 31;
                float4 v = *(const float4*)(Bm + (size_t)(kc + k) * 128 + n4 * 4);
                int k8 = k >> 3, kl = k & 7, rw = kl & 3, reg = kl >> 2;
                int nt = n4 >> 1;
                float* bs = (float*)Bs + (((k8 * 16 + nt) * 32) + (n4 & 1) * 16 + rw) * 2 + reg;
                bs[0]  = tf32r(v.x);
                bs[8]  = tf32r(v.y);
                bs[16] = tf32r(v.z);
                bs[24] = tf32r(v.w);
            }
        }
        __syncthreads();

        #pragma unroll
        for (int k8 = 0; k8 < 4; k8++) {
            float4 a0 = As[k8][wm * 2 + 0][lane];
            float4 a1 = As[k8][wm * 2 + 1][lane];
            float2 b[8];
            #pragma unroll
            for (int u = 0; u < 8; u++) b[u] = Bs[k8][wn * 8 + u][lane];
            #pragma unroll
            for (int u = 0; u < 8; u++) {
                mma_tf32(c[0][u], a0, b[u]);
                mma_tf32(c[1][u], a1, b[u]);
            }
        }
        __syncthreads();
    }

    // ---- Epilogue ----
    const int lr = lane >> 2;
    const int lc = (lane & 3) * 2;
    #pragma unroll
    for (int t = 0; t < 2; t++) {
        int m0 = row0 + wm * 32 + t * 16 + lr;
        #pragma unroll
        for (int u = 0; u < 8; u++) {
            int n = wn * 64 + u * 8 + lc;
            float b0 = bias[n], b1 = bias[n + 1];
            float v0 = c[t][u][0] + b0;
            float v1 = c[t][u][1] + b1;
            float v2 = c[t][u][2] + b0;
            float v3 = c[t][u][3] + b1;
            if (EPI == EPI_GELU) {
                v0 = 0.5f * v0 * (1.0f + erff(v0 * 0.70710678f));
                v1 = 0.5f * v1 * (1.0f + erff(v1 * 0.70710678f));
                v2 = 0.5f * v2 * (1.0f + erff(v2 * 0.70710678f));
                v3 = 0.5f * v3 * (1.0f + erff(v3 * 0.70710678f));
            } else if (EPI == EPI_RES) {
                float2 r0 = *(const float2*)(res + (size_t)m0 * 128 + n);
                float2 r1 = *(const float2*)(res + (size_t)(m0 + 8) * 128 + n);
                v0 += r0.x; v1 += r0.y; v2 += r1.x; v3 += r1.y;
            }
            *(float2*)(Cm + (size_t)m0 * 128 + n)       = make_float2(v0, v1);
            *(float2*)(Cm + (size_t)(m0 + 8) * 128 + n) = make_float2(v2, v3);
        }
    }
}

// ---------------------------------------------------------------------------
// LayerNorm over 256-wide concat, one warp per token
// ---------------------------------------------------------------------------
__global__ void ln_k(const float* __restrict__ x1a, const float* __restrict__ x2a,
                     const float* __restrict__ lw, const float* __restrict__ lb,
                     float* __restrict__ out) {
    int warp = (blockIdx.x * blockDim.x + threadIdx.x) >> 5;
    int lane = threadIdx.x & 31;
    if (warp >= Mm) return;
    float v[8];
    #pragma unroll
    for (int kq = 0; kq < 4; kq++) v[kq]     = x1a[(size_t)warp * 128 + lane + 32 * kq];
    #pragma unroll
    for (int kq = 0; kq < 4; kq++) v[4 + kq] = x2a[(size_t)warp * 128 + lane + 32 * kq];
    float s = 0.f, sq = 0.f;
    #pragma unroll
    for (int kq = 0; kq < 8; kq++) { s += v[kq]; sq += v[kq] * v[kq]; }
    #pragma unroll
    for (int o = 16; o > 0; o >>= 1) {
        s  += __shfl_xor_sync(0xffffffffu, s, o);
        sq += __shfl_xor_sync(0xffffffffu, sq, o);
    }
    float mean = s * (1.f / 256.f);
    float var  = sq * (1.f / 256.f) - mean * mean;
    float rstd = rsqrtf(var + 1e-5f);
    #pragma unroll
    for (int kq = 0; kq < 8; kq++) {
        int i = (kq < 4) ? (lane + 32 * kq) : (128 + lane + 32 * (kq - 4));
        out[(size_t)warp * 256 + i] = (v[kq] - mean) * rstd * lw[i] + lb[i];
    }
}

// ---------------------------------------------------------------------------
// Window attention (SIMT fp32), one block per 7x7 window
// ---------------------------------------------------------------------------
__global__ void attn_k(const float* __restrict__ q, const float* __restrict__ k,
                       const float* __restrict__ v, float* __restrict__ out) {
    extern __shared__ float sm[];
    float* qs = sm;
    float* ks = qs + 49 * 128;
    float* vs = ks + 49 * 128;
    __shared__ float sc[49 * 49];

    int wid = blockIdx.x;
    int b  = wid >> 6;
    int wh = (wid >> 3) & 7;
    int ww = wid & 7;
    int tid = threadIdx.x;

    for (int e = tid; e < 49 * 128; e += 256) {
        int i = e >> 7, c = e & 127;
        size_t g = ((size_t)(b * Nn + (wh * 7 + i / 7) * Ww + ww * 7 + (i % 7))) * 128 + c;
        qs[e] = q[g];
        ks[e] = k[g];
        vs[e] = v[g];
    }
    __syncthreads();

    const float scale = 0.08838834764831845f;
    for (int e = tid; e < 49 * 49; e += 256) {
        int i = e / 49, j = e % 49;
        const float* qp = qs + i * 128;
        const float* kp = ks + j * 128;
        float s = 0.f;
        #pragma unroll
        for (int c2 = 0; c2 < 128; c2 += 4) {
            float4 a  = *(const float4*)(qp + c2);
            float4 bb = *(const float4*)(kp + c2);
            s += a.x * bb.x + a.y * bb.y + a.z * bb.z + a.w * bb.w;
        }
        sc[e] = s * scale;
    }
    __syncthreads();

    if (tid < 49) {
        float* r = sc + tid * 49;
        float mx = r[0];
        #pragma unroll
        for (int j = 1; j < 49; j++) mx = fmaxf(mx, r[j]);
        float sum = 0.f;
        #pragma unroll
        for (int j = 0; j < 49; j++) { float e2 = expf(r[j] - mx); r[j] = e2; sum += e2; }
        float inv = 1.f / sum;
        #pragma unroll
        for (int j = 0; j < 49; j++) r[j] *= inv;
    }
    __syncthreads();

    for (int e = tid; e < 49 * 128; e += 256) {
        int i = e >> 7, c = e & 127;
        float s = 0.f;
        #pragma unroll 7
        for (int j = 0; j < 49; j++) s += sc[i * 49 + j] * vs[j * 128 + c];
        size_t g = ((size_t)(b * Nn + (wh * 7 + i / 7) * Ww + ww * 7 + (i % 7))) * 128 + c;
        out[g] = s;
    }
}

// ---------------------------------------------------------------------------
// BatchNorm pieces (deterministic two-stage reductions)
// ---------------------------------------------------------------------------
__global__ void bn_stats_k(const float* __restrict__ x, float* __restrict__ part) {
    int c = threadIdx.x & 127;
    int half = threadIdx.x >> 7;
    float s = 0.f, sq = 0.f;
    int rbeg = blockIdx.x * 128 + half;
    int rend = blockIdx.x * 128 + 128;
    for (int r = rbeg; r < rend; r += 2) {
        float vv = x[(size_t)r * 128 + c];
        s += vv; sq += vv * vv;
    }
    __shared__ float sh[512];
    sh[threadIdx.x] = s;
    sh[256 + threadIdx.x] = sq;
    __syncthreads();
    if (half == 0) {
        part[blockIdx.x * 256 + c]       = sh[c] + sh[128 + c];
        part[blockIdx.x * 256 + 128 + c] = sh[256 + c] + sh[256 + 128 + c];
    }
}

// apply BN1 affine + ReLU in place AND produce BN2 partial sums
__global__ void bn_apply_relu_stats_k(float* __restrict__ x,
                                      const float* __restrict__ scale,
                                      const float* __restrict__ shift,
                                      float* __restrict__ part) {
    int c = threadIdx.x & 127;
    int half = threadIdx.x >> 7;
    float sc = scale[c], sh_ = shift[c];
    float s = 0.f, sq = 0.f;
    int rbeg = blockIdx.x * 128 + half;
    int rend = blockIdx.x * 128 + 128;
    for (int r = rbeg; r < rend; r += 2) {
        float vv = fmaxf(x[(size_t)r * 128 + c] * sc + sh_, 0.f);
        x[(size_t)r * 128 + c] = vv;
        s += vv; sq += vv * vv;
    }
    __shared__ float shm[512];
    shm[threadIdx.x] = s;
    shm[256 + threadIdx.x] = sq;
    __syncthreads();
    if (half == 0) {
        part[blockIdx.x * 256 + c]       = shm[c] + shm[128 + c];
        part[blockIdx.x * 256 + 128 + c] = shm[256 + c] + shm[256 + 128 + c];
    }
}

__global__ void bn_reduce_k(const float* __restrict__ part, const float* __restrict__ g,
                            const float* __restrict__ beta, float* __restrict__ scale,
                            float* __restrict__ shift) {
    int c = threadIdx.x;
    float s = 0.f, sq = 0.f;
    for (int i = 0; i < 784; i++) {
        s  += part[i * 256 + c];
        sq += part[i * 256 + 128 + c];
    }
    float mean = s / (float)Mm;
    float var  = sq / (float)Mm - mean * mean;
    float sc_  = g[c] * rsqrtf(var + 1e-5f);
    scale[c] = sc_;
    shift[c] = beta[c] - mean * sc_;
}

// ---------------------------------------------------------------------------
// Host launch
// ---------------------------------------------------------------------------
static float* symaddr(const void* devsym) {
    void* p = nullptr;
    cudaGetSymbolAddress(&p, devsym);
    return (float*)p;
}

extern "C" void kernel_launch(void* const* d_in, const int* in_sizes, int n_in,
                              void* d_out, int out_size) {
    const float* x     = (const float*)d_in[0];
    const float* fc1_w = (const float*)d_in[1];
    const float* fc1_b = (const float*)d_in[2];
    const float* fc2_w = (const float*)d_in[3];
    const float* fc2_b = (const float*)d_in[4];
    const float* fc3_w = (const float*)d_in[5];
    const float* fc3_b = (const float*)d_in[6];
    const float* fc4_w = (const float*)d_in[7];
    const float* fc4_b = (const float*)d_in[8];
    const float* fc5_w = (const float*)d_in[9];
    const float* fc5_b = (const float*)d_in[10];
    const float* fc6_w = (const float*)d_in[11];
    const float* fc6_b = (const float*)d_in[12];
    const float* ln_w  = (const float*)d_in[13];
    const float* ln_b  = (const float*)d_in[14];
    const float* q_w   = (const float*)d_in[15];
    const float* q_b   = (const float*)d_in[16];
    const float* k_w   = (const float*)d_in[17];
    const float* k_b   = (const float*)d_in[18];
    const float* v_w   = (const float*)d_in[19];
    const float* v_b   = (const float*)d_in[20];
    const float* bn1_g = (const float*)d_in[21];
    const float* bn1_b = (const float*)d_in[22];
    const float* bn2_g = (const float*)d_in[23];
    const float* bn2_b = (const float*)d_in[24];

    float* t0   = symaddr(g_t0);
    float* t1   = symaddr(g_t1);
    float* x1a  = symaddr(g_x1a);
    float* x2a  = symaddr(g_x2a);
    float* qb   = symaddr(g_q);
    float* kb   = symaddr(g_k);
    float* vb   = symaddr(g_v);
    float* att  = symaddr(g_att);
    float* lnb  = symaddr(g_ln);
    float* part = symaddr(g_part);
    float* scl  = symaddr(g_scale);
    float* shf  = symaddr(g_shift);

    const int gridR = Bb * 56;   // 1792 roll blocks
    const int gridG = Mm / 128;  // 784

    // Branch 1
    roll_k<0><<<gridR, 256>>>(x, t0);
    gemm_k<128, EPI_GELU, false, false, false><<<gridG, 256>>>(t0, nullptr, fc1_w, fc1_b, nullptr, nullptr, nullptr, t1);
    roll_k<1><<<gridR, 256>>>(t1, t0);
    gemm_k<128, EPI_RES, false, false, false><<<gridG, 256>>>(t0, nullptr, fc2_w, fc2_b, x, nullptr, nullptr, x1a);

    // Branch 2
    roll_k<2><<<gridR, 256>>>(x, t0);
    gemm_k<128, EPI_GELU, false, false, false><<<gridG, 256>>>(t0, nullptr, fc3_w, fc3_b, nullptr, nullptr, nullptr, t1);
    roll_k<0><<<gridR, 256>>>(t1, t0);
    gemm_k<128, EPI_RES, false, false, false><<<gridG, 256>>>(t0, nullptr, fc4_w, fc4_b, x, nullptr, nullptr, x2a);

    // LN + fc5 + residual -> t0 = x1 final
    ln_k<<<Mm / 8, 256>>>(x1a, x2a, ln_w, ln_b, lnb);
    gemm_k<256, EPI_RES, false, false, false><<<gridG, 256>>>(lnb, nullptr, fc5_w, fc5_b, x, nullptr, nullptr, t0);

    // q/k/v projections (weights are [Cout,Cin] -> BT layout)
    gemm_k<128, EPI_BIAS, false, true, false><<<gridG, 256>>>(x, nullptr, q_w, q_b, nullptr, nullptr, nullptr, qb);
    gemm_k<128, EPI_BIAS, false, true, false><<<gridG, 256>>>(x, nullptr, k_w, k_b, nullptr, nullptr, nullptr, kb);
    gemm_k<128, EPI_BIAS, false, true, false><<<gridG, 256>>>(x, nullptr, v_w, v_b, nullptr, nullptr, nullptr, vb);

    // Window attention
    cudaFuncSetAttribute(attn_k, cudaFuncAttributeMaxDynamicSharedMemorySize, 3 * 49 * 128 * 4);
    attn_k<<<2048, 256, 3 * 49 * 128 * 4>>>(qb, kb, vb, att);

    // BN1 stats -> (apply BN1+ReLU, BN2 stats) -> BN2 affine folded into fc6
    bn_stats_k<<<784, 256>>>(att, part);
    bn_reduce_k<<<1, 128>>>(part, bn1_g, bn1_b, scl, shf);
    bn_apply_relu_stats_k<<<784, 256>>>(att, scl, shf, part);
    bn_reduce_k<<<1, 128>>>(part, bn2_g, bn2_b, scl, shf);

    // Final: out = [x1 | BN2(att)] @ fc6 + b
    gemm_k<256, EPI_BIAS, true, false, true><<<gridG, 256>>>(t0, att, fc6_w, fc6_b, nullptr, scl, shf, (float*)d_out);
}

// round 4
// speedup vs baseline: 1.5850x; 1.1561x over previous
#include <cuda_runtime.h>
#include <math.h>
#include <stdint.h>

constexpr int Bb = 32;
constexpr int Hh = 56;
constexpr int Ww = 56;
constexpr int Cc = 128;
constexpr int Nn = Hh * Ww;              // 3136
constexpr int Mm = Bb * Nn;              // 100352
constexpr size_t MC = (size_t)Mm * Cc;

__device__ float g_t0[MC];
__device__ float g_t1[MC];
__device__ float g_x1a[MC];
__device__ float g_x2a[MC];
__device__ float g_q[MC];
__device__ float g_k[MC];
__device__ float g_v[MC];
__device__ float g_att[MC];
__device__ float g_ln[MC * 2];
__device__ float g_part[784 * 256];
__device__ float g_scale[Cc];
__device__ float g_shift[Cc];

__device__ __forceinline__ float tf32r(float x) {
    uint32_t u;
    asm("cvt.rna.tf32.f32 %0, %1;" : "=r"(u) : "f"(x));
    return __uint_as_float(u);
}

__device__ __forceinline__ void mma_tf32(float* c, const float4& a, const float2& b) {
    asm volatile(
        "mma.sync.aligned.m16n8k8.row.col.f32.tf32.tf32.f32 "
        "{%0,%1,%2,%3}, {%4,%5,%6,%7}, {%8,%9}, {%0,%1,%2,%3};"
        : "+f"(c[0]), "+f"(c[1]), "+f"(c[2]), "+f"(c[3])
        : "r"(__float_as_uint(a.x)), "r"(__float_as_uint(a.y)),
          "r"(__float_as_uint(a.z)), "r"(__float_as_uint(a.w)),
          "r"(__float_as_uint(b.x)), "r"(__float_as_uint(b.y)));
}

// ---------------------------------------------------------------------------
// Per-channel roll. MODE 0: H,+c  1: W,+c  2: W,-c
// ---------------------------------------------------------------------------
template <int MODE>
__launch_bounds__(256)
__global__ void roll_k(const float* __restrict__ in, float* __restrict__ out) {
    __shared__ float tile[56 * 128];
    const int tid = threadIdx.x;
    const int b = blockIdx.x / 56;
    const int f = blockIdx.x % 56;
    const size_t base   = (MODE == 0) ? ((size_t)b * Nn + f) * 128
                                      : ((size_t)(b * 56 + f) * 56) * 128;
    const int    stride = (MODE == 0) ? 56 * 128 : 128;

    #pragma unroll
    for (int e = tid; e < 56 * 32; e += 256) {
        int rowi = e >> 5, c4 = e & 31;
        ((float4*)tile)[rowi * 32 + c4] =
            *(const float4*)(in + base + (size_t)rowi * stride + c4 * 4);
    }
    __syncthreads();

    #pragma unroll
    for (int e = tid; e < 56 * 128; e += 256) {
        int pos = e >> 7, c = e & 127;
        int cm = c % 56;
        int src = (MODE == 2) ? pos + cm : pos - cm;
        if (src < 0) src += 56;
        if (src >= 56) src -= 56;
        out[base + (size_t)pos * stride + c] = tile[src * 128 + c];
    }
}

// ---------------------------------------------------------------------------
// TF32 GEMM, conflict-free fragment-order smem.
// Fragment layout (validated in R2):
//   A float4 at [k8][mt][lane]: {A(r,c),A(r+8,c),A(r,c+4),A(r+8,c+4)},
//     r = mt*16 + lane/4, c = k8*8 + lane%4
//   B float2 at [k8g][nt][lane]: {B(k,n),B(k+4,n)}, k = k8g*8 + lane%4, n = nt*8 + lane/4
// B resident in smem for whole K; A double-buffered with register prefetch.
// ---------------------------------------------------------------------------
enum { EPI_GELU = 0, EPI_BIAS = 1, EPI_RES = 2 };

template <int K, int EPI, bool SPLIT, bool BT, bool FOLD>
__launch_bounds__(256)
__global__ void gemm_k(const float* __restrict__ A0, const float* __restrict__ A1,
                       const float* __restrict__ Bm, const float* __restrict__ bias,
                       const float* __restrict__ res,
                       const float* __restrict__ bscl, const float* __restrict__ bshf,
                       float* __restrict__ Cm) {
    extern __shared__ float smem[];
    float2* Bs  = (float2*)smem;                  // (K/8)*16 frags * 32 lanes
    float4* As4 = (float4*)(smem + K * 128);      // 2 bufs * 4 k8 * 8 mt * 32

    const int tid  = threadIdx.x;
    const int lane = tid & 31;
    const int wid  = tid >> 5;
    const int wm   = wid & 3;
    const int wn   = wid >> 2;
    const int row0 = blockIdx.x * 128;
    const int lr   = lane >> 2;       // 0..7
    const int lc   = lane & 3;        // 0..3

    // ---- load whole B (fragment order, conflict-free STS.64) ----
    for (int frag = wid; frag < (K / 8) * 16; frag += 8) {
        int k8 = frag >> 4, nt = frag & 15;
        int kk = k8 * 8 + lc, n = nt * 8 + lr;
        float b0, b1;
        if (BT) { b0 = Bm[(size_t)n * K + kk];   b1 = Bm[(size_t)n * K + kk + 4]; }
        else    { b0 = Bm[(size_t)kk * 128 + n]; b1 = Bm[(size_t)(kk + 4) * 128 + n]; }
        Bs[frag * 32 + lane] = make_float2(tf32r(b0), tf32r(b1));
    }

    // ---- A fragment gather (4 scalars -> one float4, tf32-rounded) ----
    auto fetchA = [&](int r, int c) -> float {
        if (!SPLIT) return A0[(size_t)r * K + c];
        if (c < 128) return A0[(size_t)r * 128 + c];
        float v = A1[(size_t)r * 128 + (c - 128)];
        if (FOLD) v = v * bscl[c - 128] + bshf[c - 128];
        return v;
    };
    float4 pa[4];
    auto gather = [&](int kc) {
        int r = row0 + wid * 16 + lr;
        #pragma unroll
        for (int i = 0; i < 4; i++) {
            int c = kc + i * 8 + lc;
            pa[i] = make_float4(tf32r(fetchA(r, c)),     tf32r(fetchA(r + 8, c)),
                                tf32r(fetchA(r, c + 4)), tf32r(fetchA(r + 8, c + 4)));
        }
    };

    float acc[2][8][4] = {};
    gather(0);

    constexpr int NS = K / 32;
    #pragma unroll
    for (int s = 0; s < NS; s++) {
        const int buf = s & 1;
        #pragma unroll
        for (int i = 0; i < 4; i++)
            As4[((buf * 4 + i) * 8 + wid) * 32 + lane] = pa[i];
        __syncthreads();
        if (s + 1 < NS) gather((s + 1) * 32);
        #pragma unroll
        for (int k8 = 0; k8 < 4; k8++) {
            float4 a0 = As4[((buf * 4 + k8) * 8 + wm * 2 + 0) * 32 + lane];
            float4 a1 = As4[((buf * 4 + k8) * 8 + wm * 2 + 1) * 32 + lane];
            #pragma unroll
            for (int u = 0; u < 8; u++) {
                float2 b = Bs[((s * 4 + k8) * 16 + wn * 8 + u) * 32 + lane];
                mma_tf32(acc[0][u], a0, b);
                mma_tf32(acc[1][u], a1, b);
            }
        }
        __syncthreads();
    }

    // ---- epilogue ----
    const int ec = lc * 2;
    #pragma unroll
    for (int t = 0; t < 2; t++) {
        int m0 = row0 + wm * 32 + t * 16 + lr;
        #pragma unroll
        for (int u = 0; u < 8; u++) {
            int n = wn * 64 + u * 8 + ec;
            float b0 = bias[n], b1 = bias[n + 1];
            float v0 = acc[t][u][0] + b0;
            float v1 = acc[t][u][1] + b1;
            float v2 = acc[t][u][2] + b0;
            float v3 = acc[t][u][3] + b1;
            if (EPI == EPI_GELU) {
                v0 = 0.5f * v0 * (1.0f + erff(v0 * 0.70710678f));
                v1 = 0.5f * v1 * (1.0f + erff(v1 * 0.70710678f));
                v2 = 0.5f * v2 * (1.0f + erff(v2 * 0.70710678f));
                v3 = 0.5f * v3 * (1.0f + erff(v3 * 0.70710678f));
            } else if (EPI == EPI_RES) {
                float2 r0 = *(const float2*)(res + (size_t)m0 * 128 + n);
                float2 r1 = *(const float2*)(res + (size_t)(m0 + 8) * 128 + n);
                v0 += r0.x; v1 += r0.y; v2 += r1.x; v3 += r1.y;
            }
            *(float2*)(Cm + (size_t)m0 * 128 + n)       = make_float2(v0, v1);
            *(float2*)(Cm + (size_t)(m0 + 8) * 128 + n) = make_float2(v2, v3);
        }
    }
}

// ---------------------------------------------------------------------------
// LayerNorm over 256-wide concat
// ---------------------------------------------------------------------------
__global__ void ln_k(const float* __restrict__ x1a, const float* __restrict__ x2a,
                     const float* __restrict__ lw, const float* __restrict__ lb,
                     float* __restrict__ out) {
    int warp = (blockIdx.x * blockDim.x + threadIdx.x) >> 5;
    int lane = threadIdx.x & 31;
    if (warp >= Mm) return;
    float v[8];
    #pragma unroll
    for (int kq = 0; kq < 4; kq++) v[kq]     = x1a[(size_t)warp * 128 + lane + 32 * kq];
    #pragma unroll
    for (int kq = 0; kq < 4; kq++) v[4 + kq] = x2a[(size_t)warp * 128 + lane + 32 * kq];
    float s = 0.f, sq = 0.f;
    #pragma unroll
    for (int kq = 0; kq < 8; kq++) { s += v[kq]; sq += v[kq] * v[kq]; }
    #pragma unroll
    for (int o = 16; o > 0; o >>= 1) {
        s  += __shfl_xor_sync(0xffffffffu, s, o);
        sq += __shfl_xor_sync(0xffffffffu, sq, o);
    }
    float mean = s * (1.f / 256.f);
    float var  = sq * (1.f / 256.f) - mean * mean;
    float rstd = rsqrtf(var + 1e-5f);
    #pragma unroll
    for (int kq = 0; kq < 8; kq++) {
        int i = (kq < 4) ? (lane + 32 * kq) : (128 + lane + 32 * (kq - 4));
        out[(size_t)warp * 256 + i] = (v[kq] - mean) * rstd * lw[i] + lb[i];
    }
}

// ---------------------------------------------------------------------------
// Window attention (unchanged, SIMT fp32)
// ---------------------------------------------------------------------------
__global__ void attn_k(const float* __restrict__ q, const float* __restrict__ k,
                       const float* __restrict__ v, float* __restrict__ out) {
    extern __shared__ float sm[];
    float* qs = sm;
    float* ks = qs + 49 * 128;
    float* vs = ks + 49 * 128;
    __shared__ float sc[49 * 49];

    int wid = blockIdx.x;
    int b  = wid >> 6;
    int wh = (wid >> 3) & 7;
    int ww = wid & 7;
    int tid = threadIdx.x;

    for (int e = tid; e < 49 * 128; e += 256) {
        int i = e >> 7, c = e & 127;
        size_t g = ((size_t)(b * Nn + (wh * 7 + i / 7) * Ww + ww * 7 + (i % 7))) * 128 + c;
        qs[e] = q[g];
        ks[e] = k[g];
        vs[e] = v[g];
    }
    __syncthreads();

    const float scale = 0.08838834764831845f;
    for (int e = tid; e < 49 * 49; e += 256) {
        int i = e / 49, j = e % 49;
        const float* qp = qs + i * 128;
        const float* kp = ks + j * 128;
        float s = 0.f;
        #pragma unroll
        for (int c2 = 0; c2 < 128; c2 += 4) {
            float4 a  = *(const float4*)(qp + c2);
            float4 bb = *(const float4*)(kp + c2);
            s += a.x * bb.x + a.y * bb.y + a.z * bb.z + a.w * bb.w;
        }
        sc[e] = s * scale;
    }
    __syncthreads();

    if (tid < 49) {
        float* r = sc + tid * 49;
        float mx = r[0];
        #pragma unroll
        for (int j = 1; j < 49; j++) mx = fmaxf(mx, r[j]);
        float sum = 0.f;
        #pragma unroll
        for (int j = 0; j < 49; j++) { float e2 = expf(r[j] - mx); r[j] = e2; sum += e2; }
        float inv = 1.f / sum;
        #pragma unroll
        for (int j = 0; j < 49; j++) r[j] *= inv;
    }
    __syncthreads();

    for (int e = tid; e < 49 * 128; e += 256) {
        int i = e >> 7, c = e & 127;
        float s = 0.f;
        #pragma unroll 7
        for (int j = 0; j < 49; j++) s += sc[i * 49 + j] * vs[j * 128 + c];
        size_t g = ((size_t)(b * Nn + (wh * 7 + i / 7) * Ww + ww * 7 + (i % 7))) * 128 + c;
        out[g] = s;
    }
}

// ---------------------------------------------------------------------------
// BatchNorm pieces
// ---------------------------------------------------------------------------
__global__ void bn_stats_k(const float* __restrict__ x, float* __restrict__ part) {
    int c = threadIdx.x & 127;
    int half = threadIdx.x >> 7;
    float s = 0.f, sq = 0.f;
    int rbeg = blockIdx.x * 128 + half;
    int rend = blockIdx.x * 128 + 128;
    for (int r = rbeg; r < rend; r += 2) {
        float vv = x[(size_t)r * 128 + c];
        s += vv; sq += vv * vv;
    }
    __shared__ float sh[512];
    sh[threadIdx.x] = s;
    sh[256 + threadIdx.x] = sq;
    __syncthreads();
    if (half == 0) {
        part[blockIdx.x * 256 + c]       = sh[c] + sh[128 + c];
        part[blockIdx.x * 256 + 128 + c] = sh[256 + c] + sh[256 + 128 + c];
    }
}

__global__ void bn_apply_relu_stats_k(float* __restrict__ x,
                                      const float* __restrict__ scale,
                                      const float* __restrict__ shift,
                                      float* __restrict__ part) {
    int c = threadIdx.x & 127;
    int half = threadIdx.x >> 7;
    float sc = scale[c], sh_ = shift[c];
    float s = 0.f, sq = 0.f;
    int rbeg = blockIdx.x * 128 + half;
    int rend = blockIdx.x * 128 + 128;
    for (int r = rbeg; r < rend; r += 2) {
        float vv = fmaxf(x[(size_t)r * 128 + c] * sc + sh_, 0.f);
        x[(size_t)r * 128 + c] = vv;
        s += vv; sq += vv * vv;
    }
    __shared__ float shm[512];
    shm[threadIdx.x] = s;
    shm[256 + threadIdx.x] = sq;
    __syncthreads();
    if (half == 0) {
        part[blockIdx.x * 256 + c]       = shm[c] + shm[128 + c];
        part[blockIdx.x * 256 + 128 + c] = shm[256 + c] + shm[256 + 128 + c];
    }
}

__global__ void bn_reduce_k(const float* __restrict__ part, const float* __restrict__ g,
                            const float* __restrict__ beta, float* __restrict__ scale,
                            float* __restrict__ shift) {
    int c = threadIdx.x;
    float s = 0.f, sq = 0.f;
    for (int i = 0; i < 784; i++) {
        s  += part[i * 256 + c];
        sq += part[i * 256 + 128 + c];
    }
    float mean = s / (float)Mm;
    float var  = sq / (float)Mm - mean * mean;
    float sc_  = g[c] * rsqrtf(var + 1e-5f);
    scale[c] = sc_;
    shift[c] = beta[c] - mean * sc_;
}

// ---------------------------------------------------------------------------
// Host launch
// ---------------------------------------------------------------------------
static float* symaddr(const void* devsym) {
    void* p = nullptr;
    cudaGetSymbolAddress(&p, devsym);
    return (float*)p;
}

extern "C" void kernel_launch(void* const* d_in, const int* in_sizes, int n_in,
                              void* d_out, int out_size) {
    const float* x     = (const float*)d_in[0];
    const float* fc1_w = (const float*)d_in[1];
    const float* fc1_b = (const float*)d_in[2];
    const float* fc2_w = (const float*)d_in[3];
    const float* fc2_b = (const float*)d_in[4];
    const float* fc3_w = (const float*)d_in[5];
    const float* fc3_b = (const float*)d_in[6];
    const float* fc4_w = (const float*)d_in[7];
    const float* fc4_b = (const float*)d_in[8];
    const float* fc5_w = (const float*)d_in[9];
    const float* fc5_b = (const float*)d_in[10];
    const float* fc6_w = (const float*)d_in[11];
    const float* fc6_b = (const float*)d_in[12];
    const float* ln_w  = (const float*)d_in[13];
    const float* ln_b  = (const float*)d_in[14];
    const float* q_w   = (const float*)d_in[15];
    const float* q_b   = (const float*)d_in[16];
    const float* k_w   = (const float*)d_in[17];
    const float* k_b   = (const float*)d_in[18];
    const float* v_w   = (const float*)d_in[19];
    const float* v_b   = (const float*)d_in[20];
    const float* bn1_g = (const float*)d_in[21];
    const float* bn1_b = (const float*)d_in[22];
    const float* bn2_g = (const float*)d_in[23];
    const float* bn2_b = (const float*)d_in[24];

    float* t0   = symaddr(g_t0);
    float* t1   = symaddr(g_t1);
    float* x1a  = symaddr(g_x1a);
    float* x2a  = symaddr(g_x2a);
    float* qb   = symaddr(g_q);
    float* kb   = symaddr(g_k);
    float* vb   = symaddr(g_v);
    float* att  = symaddr(g_att);
    float* lnb  = symaddr(g_ln);
    float* part = symaddr(g_part);
    float* scl  = symaddr(g_scale);
    float* shf  = symaddr(g_shift);

    const int gridR = Bb * 56;
    const int gridG = Mm / 128;          // 784
    const int SM128 = (128 * 128 + 2 * 4096) * 4;   // 96 KB
    const int SM256 = (256 * 128 + 2 * 4096) * 4;   // 160 KB

    cudaFuncSetAttribute(gemm_k<128, EPI_GELU, false, false, false>, cudaFuncAttributeMaxDynamicSharedMemorySize, SM128);
    cudaFuncSetAttribute(gemm_k<128, EPI_RES,  false, false, false>, cudaFuncAttributeMaxDynamicSharedMemorySize, SM128);
    cudaFuncSetAttribute(gemm_k<128, EPI_BIAS, false, true,  false>, cudaFuncAttributeMaxDynamicSharedMemorySize, SM128);
    cudaFuncSetAttribute(gemm_k<256, EPI_RES,  false, false, false>, cudaFuncAttributeMaxDynamicSharedMemorySize, SM256);
    cudaFuncSetAttribute(gemm_k<256, EPI_BIAS, true,  false, true >, cudaFuncAttributeMaxDynamicSharedMemorySize, SM256);

    // Branch 1
    roll_k<0><<<gridR, 256>>>(x, t0);
    gemm_k<128, EPI_GELU, false, false, false><<<gridG, 256, SM128>>>(t0, nullptr, fc1_w, fc1_b, nullptr, nullptr, nullptr, t1);
    roll_k<1><<<gridR, 256>>>(t1, t0);
    gemm_k<128, EPI_RES, false, false, false><<<gridG, 256, SM128>>>(t0, nullptr, fc2_w, fc2_b, x, nullptr, nullptr, x1a);

    // Branch 2
    roll_k<2><<<gridR, 256>>>(x, t0);
    gemm_k<128, EPI_GELU, false, false, false><<<gridG, 256, SM128>>>(t0, nullptr, fc3_w, fc3_b, nullptr, nullptr, nullptr, t1);
    roll_k<0><<<gridR, 256>>>(t1, t0);
    gemm_k<128, EPI_RES, false, false, false><<<gridG, 256, SM128>>>(t0, nullptr, fc4_w, fc4_b, x, nullptr, nullptr, x2a);

    // LN + fc5 + residual
    ln_k<<<Mm / 8, 256>>>(x1a, x2a, ln_w, ln_b, lnb);
    gemm_k<256, EPI_RES, false, false, false><<<gridG, 256, SM256>>>(lnb, nullptr, fc5_w, fc5_b, x, nullptr, nullptr, t0);

    // q/k/v projections (weights [Cout,Cin] -> BT)
    gemm_k<128, EPI_BIAS, false, true, false><<<gridG, 256, SM128>>>(x, nullptr, q_w, q_b, nullptr, nullptr, nullptr, qb);
    gemm_k<128, EPI_BIAS, false, true, false><<<gridG, 256, SM128>>>(x, nullptr, k_w, k_b, nullptr, nullptr, nullptr, kb);
    gemm_k<128, EPI_BIAS, false, true, false><<<gridG, 256, SM128>>>(x, nullptr, v_w, v_b, nullptr, nullptr, nullptr, vb);

    // Window attention
    cudaFuncSetAttribute(attn_k, cudaFuncAttributeMaxDynamicSharedMemorySize, 3 * 49 * 128 * 4);
    attn_k<<<2048, 256, 3 * 49 * 128 * 4>>>(qb, kb, vb, att);

    // BN1 -> (apply+ReLU, BN2 stats) -> BN2 folded into fc6 A-load
    bn_stats_k<<<784, 256>>>(att, part);
    bn_reduce_k<<<1, 128>>>(part, bn1_g, bn1_b, scl, shf);
    bn_apply_relu_stats_k<<<784, 256>>>(att, scl, shf, part);
    bn_reduce_k<<<1, 128>>>(part, bn2_g, bn2_b, scl, shf);

    // Final: out = [x1 | BN2(att)] @ fc6 + b
    gemm_k<256, EPI_BIAS, true, false, true><<<gridG, 256, SM256>>>(t0, att, fc6_w, fc6_b, nullptr, scl, shf, (float*)d_out);
}

// round 5
// speedup vs baseline: 2.7395x; 1.7283x over previous
#include <cuda_runtime.h>
#include <math.h>
#include <stdint.h>

constexpr int Bb = 32;
constexpr int Hh = 56;
constexpr int Ww = 56;
constexpr int Cc = 128;
constexpr int Nn = Hh * Ww;              // 3136
constexpr int Mm = Bb * Nn;              // 100352
constexpr size_t MC = (size_t)Mm * Cc;

__device__ float g_t0[MC];
__device__ float g_t1[MC];
__device__ float g_x1a[MC];
__device__ float g_x2a[MC];
__device__ float g_q[MC];
__device__ float g_k[MC];
__device__ float g_v[MC];
__device__ float g_att[MC];
__device__ float g_ln[MC * 2];
__device__ float g_part[784 * 256];
__device__ float g_scale[Cc];
__device__ float g_shift[Cc];

__device__ __forceinline__ float tf32r(float x) {
    uint32_t u;
    asm("cvt.rna.tf32.f32 %0, %1;" : "=r"(u) : "f"(x));
    return __uint_as_float(u);
}

__device__ __forceinline__ void mma_tf32(float* c, const float4& a, const float2& b) {
    asm volatile(
        "mma.sync.aligned.m16n8k8.row.col.f32.tf32.tf32.f32 "
        "{%0,%1,%2,%3}, {%4,%5,%6,%7}, {%8,%9}, {%0,%1,%2,%3};"
        : "+f"(c[0]), "+f"(c[1]), "+f"(c[2]), "+f"(c[3])
        : "r"(__float_as_uint(a.x)), "r"(__float_as_uint(a.y)),
          "r"(__float_as_uint(a.z)), "r"(__float_as_uint(a.w)),
          "r"(__float_as_uint(b.x)), "r"(__float_as_uint(b.y)));
}

// ---------------------------------------------------------------------------
// Per-channel roll. MODE 0: H,+c  1: W,+c  2: W,-c
// ---------------------------------------------------------------------------
template <int MODE>
__launch_bounds__(256)
__global__ void roll_k(const float* __restrict__ in, float* __restrict__ out) {
    __shared__ float tile[56 * 128];
    const int tid = threadIdx.x;
    const int b = blockIdx.x / 56;
    const int f = blockIdx.x % 56;
    const size_t base   = (MODE == 0) ? ((size_t)b * Nn + f) * 128
                                      : ((size_t)(b * 56 + f) * 56) * 128;
    const int    stride = (MODE == 0) ? 56 * 128 : 128;

    #pragma unroll
    for (int e = tid; e < 56 * 32; e += 256) {
        int rowi = e >> 5, c4 = e & 31;
        ((float4*)tile)[rowi * 32 + c4] =
            *(const float4*)(in + base + (size_t)rowi * stride + c4 * 4);
    }
    __syncthreads();

    #pragma unroll
    for (int e = tid; e < 56 * 128; e += 256) {
        int pos = e >> 7, c = e & 127;
        int cm = c % 56;
        int src = (MODE == 2) ? pos + cm : pos - cm;
        if (src < 0) src += 56;
        if (src >= 56) src -= 56;
        out[base + (size_t)pos * stride + c] = tile[src * 128 + c];
    }
}

// ---------------------------------------------------------------------------
// TF32 GEMM, conflict-free fragment-order smem. (R4 kernel + 2-CTA reg cap.)
// ---------------------------------------------------------------------------
enum { EPI_GELU = 0, EPI_BIAS = 1, EPI_RES = 2 };

template <int K, int EPI, bool SPLIT, bool BT, bool FOLD>
__launch_bounds__(256, 2)
__global__ void gemm_k(const float* __restrict__ A0, const float* __restrict__ A1,
                       const float* __restrict__ Bm, const float* __restrict__ bias,
                       const float* __restrict__ res,
                       const float* __restrict__ bscl, const float* __restrict__ bshf,
                       float* __restrict__ Cm) {
    extern __shared__ float smem[];
    float2* Bs  = (float2*)smem;
    float4* As4 = (float4*)(smem + K * 128);

    const int tid  = threadIdx.x;
    const int lane = tid & 31;
    const int wid  = tid >> 5;
    const int wm   = wid & 3;
    const int wn   = wid >> 2;
    const int row0 = blockIdx.x * 128;
    const int lr   = lane >> 2;
    const int lc   = lane & 3;

    for (int frag = wid; frag < (K / 8) * 16; frag += 8) {
        int k8 = frag >> 4, nt = frag & 15;
        int kk = k8 * 8 + lc, n = nt * 8 + lr;
        float b0, b1;
        if (BT) { b0 = Bm[(size_t)n * K + kk];   b1 = Bm[(size_t)n * K + kk + 4]; }
        else    { b0 = Bm[(size_t)kk * 128 + n]; b1 = Bm[(size_t)(kk + 4) * 128 + n]; }
        Bs[frag * 32 + lane] = make_float2(tf32r(b0), tf32r(b1));
    }

    auto fetchA = [&](int r, int c) -> float {
        if (!SPLIT) return A0[(size_t)r * K + c];
        if (c < 128) return A0[(size_t)r * 128 + c];
        float v = A1[(size_t)r * 128 + (c - 128)];
        if (FOLD) v = v * bscl[c - 128] + bshf[c - 128];
        return v;
    };
    float4 pa[4];
    auto gather = [&](int kc) {
        int r = row0 + wid * 16 + lr;
        #pragma unroll
        for (int i = 0; i < 4; i++) {
            int c = kc + i * 8 + lc;
            pa[i] = make_float4(tf32r(fetchA(r, c)),     tf32r(fetchA(r + 8, c)),
                                tf32r(fetchA(r, c + 4)), tf32r(fetchA(r + 8, c + 4)));
        }
    };

    float acc[2][8][4] = {};
    gather(0);

    constexpr int NS = K / 32;
    #pragma unroll
    for (int s = 0; s < NS; s++) {
        const int buf = s & 1;
        #pragma unroll
        for (int i = 0; i < 4; i++)
            As4[((buf * 4 + i) * 8 + wid) * 32 + lane] = pa[i];
        __syncthreads();
        if (s + 1 < NS) gather((s + 1) * 32);
        #pragma unroll
        for (int k8 = 0; k8 < 4; k8++) {
            float4 a0 = As4[((buf * 4 + k8) * 8 + wm * 2 + 0) * 32 + lane];
            float4 a1 = As4[((buf * 4 + k8) * 8 + wm * 2 + 1) * 32 + lane];
            #pragma unroll
            for (int u = 0; u < 8; u++) {
                float2 b = Bs[((s * 4 + k8) * 16 + wn * 8 + u) * 32 + lane];
                mma_tf32(acc[0][u], a0, b);
                mma_tf32(acc[1][u], a1, b);
            }
        }
        __syncthreads();
    }

    const int ec = lc * 2;
    #pragma unroll
    for (int t = 0; t < 2; t++) {
        int m0 = row0 + wm * 32 + t * 16 + lr;
        #pragma unroll
        for (int u = 0; u < 8; u++) {
            int n = wn * 64 + u * 8 + ec;
            float b0 = bias[n], b1 = bias[n + 1];
            float v0 = acc[t][u][0] + b0;
            float v1 = acc[t][u][1] + b1;
            float v2 = acc[t][u][2] + b0;
            float v3 = acc[t][u][3] + b1;
            if (EPI == EPI_GELU) {
                v0 = 0.5f * v0 * (1.0f + erff(v0 * 0.70710678f));
                v1 = 0.5f * v1 * (1.0f + erff(v1 * 0.70710678f));
                v2 = 0.5f * v2 * (1.0f + erff(v2 * 0.70710678f));
                v3 = 0.5f * v3 * (1.0f + erff(v3 * 0.70710678f));
            } else if (EPI == EPI_RES) {
                float2 r0 = *(const float2*)(res + (size_t)m0 * 128 + n);
                float2 r1 = *(const float2*)(res + (size_t)(m0 + 8) * 128 + n);
                v0 += r0.x; v1 += r0.y; v2 += r1.x; v3 += r1.y;
            }
            *(float2*)(Cm + (size_t)m0 * 128 + n)       = make_float2(v0, v1);
            *(float2*)(Cm + (size_t)(m0 + 8) * 128 + n) = make_float2(v2, v3);
        }
    }
}

// ---------------------------------------------------------------------------
// LayerNorm over 256-wide concat
// ---------------------------------------------------------------------------
__global__ void ln_k(const float* __restrict__ x1a, const float* __restrict__ x2a,
                     const float* __restrict__ lw, const float* __restrict__ lb,
                     float* __restrict__ out) {
    int warp = (blockIdx.x * blockDim.x + threadIdx.x) >> 5;
    int lane = threadIdx.x & 31;
    if (warp >= Mm) return;
    float v[8];
    #pragma unroll
    for (int kq = 0; kq < 4; kq++) v[kq]     = x1a[(size_t)warp * 128 + lane + 32 * kq];
    #pragma unroll
    for (int kq = 0; kq < 4; kq++) v[4 + kq] = x2a[(size_t)warp * 128 + lane + 32 * kq];
    float s = 0.f, sq = 0.f;
    #pragma unroll
    for (int kq = 0; kq < 8; kq++) { s += v[kq]; sq += v[kq] * v[kq]; }
    #pragma unroll
    for (int o = 16; o > 0; o >>= 1) {
        s  += __shfl_xor_sync(0xffffffffu, s, o);
        sq += __shfl_xor_sync(0xffffffffu, sq, o);
    }
    float mean = s * (1.f / 256.f);
    float var  = sq * (1.f / 256.f) - mean * mean;
    float rstd = rsqrtf(var + 1e-5f);
    #pragma unroll
    for (int kq = 0; kq < 8; kq++) {
        int i = (kq < 4) ? (lane + 32 * kq) : (128 + lane + 32 * (kq - 4));
        out[(size_t)warp * 256 + i] = (v[kq] - mean) * rstd * lw[i] + lb[i];
    }
}

// ---------------------------------------------------------------------------
// Window attention on tensor cores. One block per 7x7 window.
// Padded strides: Q/K 132, V 136, P 68 -> all fragment LDS conflict-free.
// ---------------------------------------------------------------------------
constexpr int QS_STRIDE = 132;
constexpr int VS_STRIDE = 136;
constexpr int PS_STRIDE = 68;
constexpr int ATTN_SMEM = (2 * 64 * QS_STRIDE + 64 * VS_STRIDE + 64 * PS_STRIDE) * 4;

__launch_bounds__(256)
__global__ void attn_k(const float* __restrict__ q, const float* __restrict__ k,
                       const float* __restrict__ v, float* __restrict__ out) {
    extern __shared__ float sm[];
    float* Qs = sm;
    float* Ks = Qs + 64 * QS_STRIDE;
    float* Vs = Ks + 64 * QS_STRIDE;
    float* Ps = Vs + 64 * VS_STRIDE;

    const int widx = blockIdx.x;
    const int b = widx >> 6, wh = (widx >> 3) & 7, ww = widx & 7;
    const int tid  = threadIdx.x;
    const int lane = tid & 31, w = tid >> 5;
    const int wm = w & 3, wn = w >> 2;
    const int lr = lane >> 2, lc = lane & 3;

    auto grow = [&](int i) -> size_t {
        return ((size_t)(b * Nn + (wh * 7 + i / 7) * 56 + ww * 7 + (i % 7))) * 128;
    };

    // load 49 tokens x 128 channels of q,k,v (tf32-rounded)
    for (int e = tid; e < 49 * 32; e += 256) {
        int i = e >> 5, c4 = (e & 31) * 4;
        size_t g = grow(i) + c4;
        float4 a  = *(const float4*)(q + g);
        float4 kk = *(const float4*)(k + g);
        float4 vv = *(const float4*)(v + g);
        *(float4*)(Qs + i * QS_STRIDE + c4) =
            make_float4(tf32r(a.x), tf32r(a.y), tf32r(a.z), tf32r(a.w));
        *(float4*)(Ks + i * QS_STRIDE + c4) =
            make_float4(tf32r(kk.x), tf32r(kk.y), tf32r(kk.z), tf32r(kk.w));
        *(float4*)(Vs + i * VS_STRIDE + c4) =
            make_float4(tf32r(vv.x), tf32r(vv.y), tf32r(vv.z), tf32r(vv.w));
    }
    // zero padded rows 49..63 (prevents NaN/Inf paths)
    for (int e = tid; e < 15 * QS_STRIDE; e += 256) {
        Qs[49 * QS_STRIDE + e] = 0.f;
        Ks[49 * QS_STRIDE + e] = 0.f;
    }
    for (int e = tid; e < 15 * VS_STRIDE; e += 256) Vs[49 * VS_STRIDE + e] = 0.f;
    __syncthreads();

    // S = Q K^T : warp tile m16 x n32 (8 warps: 4m x 2n)
    float acc[4][4] = {};
    #pragma unroll
    for (int k8 = 0; k8 < 16; k8++) {
        int r = wm * 16 + lr, c = k8 * 8 + lc;
        float4 a = make_float4(Qs[r * QS_STRIDE + c],       Qs[(r + 8) * QS_STRIDE + c],
                               Qs[r * QS_STRIDE + c + 4],   Qs[(r + 8) * QS_STRIDE + c + 4]);
        #pragma unroll
        for (int u = 0; u < 4; u++) {
            int n = wn * 32 + u * 8 + lr;
            float2 bf = make_float2(Ks[n * QS_STRIDE + c], Ks[n * QS_STRIDE + c + 4]);
            mma_tf32(acc[u], a, bf);
        }
    }
    #pragma unroll
    for (int u = 0; u < 4; u++) {
        int r = wm * 16 + lr, n = wn * 32 + u * 8 + lc * 2;
        *(float2*)(Ps + r * PS_STRIDE + n)       = make_float2(acc[u][0], acc[u][1]);
        *(float2*)(Ps + (r + 8) * PS_STRIDE + n) = make_float2(acc[u][2], acc[u][3]);
    }
    __syncthreads();

    // softmax rows 0..48 over cols 0..48 (scaled), zero padded cols, P -> tf32
    if (tid < 49) {
        const float scale = 0.08838834764831845f;   // 128^-0.5
        float* r = Ps + tid * PS_STRIDE;
        float mx = r[0];
        #pragma unroll 7
        for (int j = 1; j < 49; j++) mx = fmaxf(mx, r[j]);
        float s = 0.f;
        #pragma unroll 7
        for (int j = 0; j < 49; j++) { float e = expf((r[j] - mx) * scale); r[j] = e; s += e; }
        float inv = 1.f / s;
        #pragma unroll 7
        for (int j = 0; j < 49; j++) r[j] = tf32r(r[j] * inv);
        #pragma unroll
        for (int j = 49; j < 64; j++) r[j] = 0.f;
    }
    __syncthreads();

    // O = P V : warp tile m16 x n64
    float o[8][4] = {};
    #pragma unroll
    for (int k8 = 0; k8 < 8; k8++) {
        int r = wm * 16 + lr, c = k8 * 8 + lc;
        float4 a = make_float4(Ps[r * PS_STRIDE + c],     Ps[(r + 8) * PS_STRIDE + c],
                               Ps[r * PS_STRIDE + c + 4], Ps[(r + 8) * PS_STRIDE + c + 4]);
        #pragma unroll
        for (int u = 0; u < 8; u++) {
            int n = wn * 64 + u * 8 + lr;
            float2 bf = make_float2(Vs[c * VS_STRIDE + n], Vs[(c + 4) * VS_STRIDE + n]);
            mma_tf32(o[u], a, bf);
        }
    }
    int r0 = wm * 16 + lr;
    #pragma unroll
    for (int u = 0; u < 8; u++) {
        int n = wn * 64 + u * 8 + lc * 2;
        if (r0 < 49)     *(float2*)(out + grow(r0) + n)     = make_float2(o[u][0], o[u][1]);
        if (r0 + 8 < 49) *(float2*)(out + grow(r0 + 8) + n) = make_float2(o[u][2], o[u][3]);
    }
}

// ---------------------------------------------------------------------------
// BatchNorm pieces
// ---------------------------------------------------------------------------
__global__ void bn_stats_k(const float* __restrict__ x, float* __restrict__ part) {
    int c = threadIdx.x & 127;
    int half = threadIdx.x >> 7;
    float s = 0.f, sq = 0.f;
    int rbeg = blockIdx.x * 128 + half;
    int rend = blockIdx.x * 128 + 128;
    for (int r = rbeg; r < rend; r += 2) {
        float vv = x[(size_t)r * 128 + c];
        s += vv; sq += vv * vv;
    }
    __shared__ float sh[512];
    sh[threadIdx.x] = s;
    sh[256 + threadIdx.x] = sq;
    __syncthreads();
    if (half == 0) {
        part[blockIdx.x * 256 + c]       = sh[c] + sh[128 + c];
        part[blockIdx.x * 256 + 128 + c] = sh[256 + c] + sh[256 + 128 + c];
    }
}

__global__ void bn_apply_relu_stats_k(float* __restrict__ x,
                                      const float* __restrict__ scale,
                                      const float* __restrict__ shift,
                                      float* __restrict__ part) {
    int c = threadIdx.x & 127;
    int half = threadIdx.x >> 7;
    float sc = scale[c], sh_ = shift[c];
    float s = 0.f, sq = 0.f;
    int rbeg = blockIdx.x * 128 + half;
    int rend = blockIdx.x * 128 + 128;
    for (int r = rbeg; r < rend; r += 2) {
        float vv = fmaxf(x[(size_t)r * 128 + c] * sc + sh_, 0.f);
        x[(size_t)r * 128 + c] = vv;
        s += vv; sq += vv * vv;
    }
    __shared__ float shm[512];
    shm[threadIdx.x] = s;
    shm[256 + threadIdx.x] = sq;
    __syncthreads();
    if (half == 0) {
        part[blockIdx.x * 256 + c]       = shm[c] + shm[128 + c];
        part[blockIdx.x * 256 + 128 + c] = shm[256 + c] + shm[256 + 128 + c];
    }
}

__global__ void bn_reduce_k(const float* __restrict__ part, const float* __restrict__ g,
                            const float* __restrict__ beta, float* __restrict__ scale,
                            float* __restrict__ shift) {
    int c = threadIdx.x;
    float s = 0.f, sq = 0.f;
    for (int i = 0; i < 784; i++) {
        s  += part[i * 256 + c];
        sq += part[i * 256 + 128 + c];
    }
    float mean = s / (float)Mm;
    float var  = sq / (float)Mm - mean * mean;
    float sc_  = g[c] * rsqrtf(var + 1e-5f);
    scale[c] = sc_;
    shift[c] = beta[c] - mean * sc_;
}

// ---------------------------------------------------------------------------
// Host launch
// ---------------------------------------------------------------------------
static float* symaddr(const void* devsym) {
    void* p = nullptr;
    cudaGetSymbolAddress(&p, devsym);
    return (float*)p;
}

extern "C" void kernel_launch(void* const* d_in, const int* in_sizes, int n_in,
                              void* d_out, int out_size) {
    const float* x     = (const float*)d_in[0];
    const float* fc1_w = (const float*)d_in[1];
    const float* fc1_b = (const float*)d_in[2];
    const float* fc2_w = (const float*)d_in[3];
    const float* fc2_b = (const float*)d_in[4];
    const float* fc3_w = (const float*)d_in[5];
    const float* fc3_b = (const float*)d_in[6];
    const float* fc4_w = (const float*)d_in[7];
    const float* fc4_b = (const float*)d_in[8];
    const float* fc5_w = (const float*)d_in[9];
    const float* fc5_b = (const float*)d_in[10];
    const float* fc6_w = (const float*)d_in[11];
    const float* fc6_b = (const float*)d_in[12];
    const float* ln_w  = (const float*)d_in[13];
    const float* ln_b  = (const float*)d_in[14];
    const float* q_w   = (const float*)d_in[15];
    const float* q_b   = (const float*)d_in[16];
    const float* k_w   = (const float*)d_in[17];
    const float* k_b   = (const float*)d_in[18];
    const float* v_w   = (const float*)d_in[19];
    const float* v_b   = (const float*)d_in[20];
    const float* bn1_g = (const float*)d_in[21];
    const float* bn1_b = (const float*)d_in[22];
    const float* bn2_g = (const float*)d_in[23];
    const float* bn2_b = (const float*)d_in[24];

    float* t0   = symaddr(g_t0);
    float* t1   = symaddr(g_t1);
    float* x1a  = symaddr(g_x1a);
    float* x2a  = symaddr(g_x2a);
    float* qb   = symaddr(g_q);
    float* kb   = symaddr(g_k);
    float* vb   = symaddr(g_v);
    float* att  = symaddr(g_att);
    float* lnb  = symaddr(g_ln);
    float* part = symaddr(g_part);
    float* scl  = symaddr(g_scale);
    float* shf  = symaddr(g_shift);

    const int gridR = Bb * 56;
    const int gridG = Mm / 128;          // 784
    const int SM128 = (128 * 128 + 2 * 4096) * 4;   // 96 KB
    const int SM256 = (256 * 128 + 2 * 4096) * 4;   // 160 KB

    cudaFuncSetAttribute(gemm_k<128, EPI_GELU, false, false, false>, cudaFuncAttributeMaxDynamicSharedMemorySize, SM128);
    cudaFuncSetAttribute(gemm_k<128, EPI_RES,  false, false, false>, cudaFuncAttributeMaxDynamicSharedMemorySize, SM128);
    cudaFuncSetAttribute(gemm_k<128, EPI_BIAS, false, true,  false>, cudaFuncAttributeMaxDynamicSharedMemorySize, SM128);
    cudaFuncSetAttribute(gemm_k<256, EPI_RES,  false, false, false>, cudaFuncAttributeMaxDynamicSharedMemorySize, SM256);
    cudaFuncSetAttribute(gemm_k<256, EPI_BIAS, true,  false, true >, cudaFuncAttributeMaxDynamicSharedMemorySize, SM256);
    cudaFuncSetAttribute(attn_k, cudaFuncAttributeMaxDynamicSharedMemorySize, ATTN_SMEM);

    // Branch 1
    roll_k<0><<<gridR, 256>>>(x, t0);
    gemm_k<128, EPI_GELU, false, false, false><<<gridG, 256, SM128>>>(t0, nullptr, fc1_w, fc1_b, nullptr, nullptr, nullptr, t1);
    roll_k<1><<<gridR, 256>>>(t1, t0);
    gemm_k<128, EPI_RES, false, false, false><<<gridG, 256, SM128>>>(t0, nullptr, fc2_w, fc2_b, x, nullptr, nullptr, x1a);

    // Branch 2
    roll_k<2><<<gridR, 256>>>(x, t0);
    gemm_k<128, EPI_GELU, false, false, false><<<gridG, 256, SM128>>>(t0, nullptr, fc3_w, fc3_b, nullptr, nullptr, nullptr, t1);
    roll_k<0><<<gridR, 256>>>(t1, t0);
    gemm_k<128, EPI_RES, false, false, false><<<gridG, 256, SM128>>>(t0, nullptr, fc4_w, fc4_b, x, nullptr, nullptr, x2a);

    // LN + fc5 + residual
    ln_k<<<Mm / 8, 256>>>(x1a, x2a, ln_w, ln_b, lnb);
    gemm_k<256, EPI_RES, false, false, false><<<gridG, 256, SM256>>>(lnb, nullptr, fc5_w, fc5_b, x, nullptr, nullptr, t0);

    // q/k/v projections (weights [Cout,Cin] -> BT)
    gemm_k<128, EPI_BIAS, false, true, false><<<gridG, 256, SM128>>>(x, nullptr, q_w, q_b, nullptr, nullptr, nullptr, qb);
    gemm_k<128, EPI_BIAS, false, true, false><<<gridG, 256, SM128>>>(x, nullptr, k_w, k_b, nullptr, nullptr, nullptr, kb);
    gemm_k<128, EPI_BIAS, false, true, false><<<gridG, 256, SM128>>>(x, nullptr, v_w, v_b, nullptr, nullptr, nullptr, vb);

    // Window attention (tensor cores)
    attn_k<<<2048, 256, ATTN_SMEM>>>(qb, kb, vb, att);

    // BN1 -> (apply+ReLU, BN2 stats) -> BN2 folded into fc6 A-load
    bn_stats_k<<<784, 256>>>(att, part);
    bn_reduce_k<<<1, 128>>>(part, bn1_g, bn1_b, scl, shf);
    bn_apply_relu_stats_k<<<784, 256>>>(att, scl, shf, part);
    bn_reduce_k<<<1, 128>>>(part, bn2_g, bn2_b, scl, shf);

    // Final: out = [x1 | BN2(att)] @ fc6 + b
    gemm_k<256, EPI_BIAS, true, false, true><<<gridG, 256, SM256>>>(t0, att, fc6_w, fc6_b, nullptr, scl, shf, (float*)d_out);
}

// round 6
// speedup vs baseline: 2.9339x; 1.0709x over previous
#include <cuda_runtime.h>
#include <math.h>
#include <stdint.h>

constexpr int Bb = 32;
constexpr int Hh = 56;
constexpr int Ww = 56;
constexpr int Cc = 128;
constexpr int Nn = Hh * Ww;              // 3136
constexpr int Mm = Bb * Nn;              // 100352
constexpr size_t MC = (size_t)Mm * Cc;

__device__ float g_t0[MC];
__device__ float g_t1[MC];
__device__ float g_x1a[MC];
__device__ float g_x2a[MC];
__device__ float g_q[MC];
__device__ float g_k[MC];
__device__ float g_v[MC];
__device__ float g_att[MC];
__device__ float g_stats[2 * Mm];        // LN mean | rstd
__device__ float g_part[784 * 256];
__device__ float g_scale[Cc];
__device__ float g_shift[Cc];

__device__ __forceinline__ float tf32r(float x) {
    uint32_t u;
    asm("cvt.rna.tf32.f32 %0, %1;" : "=r"(u) : "f"(x));
    return __uint_as_float(u);
}

__device__ __forceinline__ void mma_tf32(float* c, const float4& a, const float2& b) {
    asm volatile(
        "mma.sync.aligned.m16n8k8.row.col.f32.tf32.tf32.f32 "
        "{%0,%1,%2,%3}, {%4,%5,%6,%7}, {%8,%9}, {%0,%1,%2,%3};"
        : "+f"(c[0]), "+f"(c[1]), "+f"(c[2]), "+f"(c[3])
        : "r"(__float_as_uint(a.x)), "r"(__float_as_uint(a.y)),
          "r"(__float_as_uint(a.z)), "r"(__float_as_uint(a.w)),
          "r"(__float_as_uint(b.x)), "r"(__float_as_uint(b.y)));
}

// ---------------------------------------------------------------------------
// Per-channel roll. MODE 0: H,+c  1: W,+c  2: W,-c
// ---------------------------------------------------------------------------
template <int MODE>
__launch_bounds__(256)
__global__ void roll_k(const float* __restrict__ in, float* __restrict__ out) {
    __shared__ float tile[56 * 128];
    const int tid = threadIdx.x;
    const int b = blockIdx.x / 56;
    const int f = blockIdx.x % 56;
    const size_t base   = (MODE == 0) ? ((size_t)b * Nn + f) * 128
                                      : ((size_t)(b * 56 + f) * 56) * 128;
    const int    stride = (MODE == 0) ? 56 * 128 : 128;

    #pragma unroll
    for (int e = tid; e < 56 * 32; e += 256) {
        int rowi = e >> 5, c4 = e & 31;
        ((float4*)tile)[rowi * 32 + c4] =
            *(const float4*)(in + base + (size_t)rowi * stride + c4 * 4);
    }
    __syncthreads();

    #pragma unroll
    for (int e = tid; e < 56 * 128; e += 256) {
        int pos = e >> 7, c = e & 127;
        int cm = c % 56;
        int src = (MODE == 2) ? pos + cm : pos - cm;
        if (src < 0) src += 56;
        if (src >= 56) src -= 56;
        out[base + (size_t)pos * stride + c] = tile[src * 128 + c];
    }
}

// ---------------------------------------------------------------------------
// TF32 GEMM, fragment-order smem (conflict-free), B chunked 128 k-cols at a
// time (96 KB smem for any K -> 2 CTAs/SM). A double-buffered reg prefetch.
// AMODE: 0 plain A[M,K]; 1 split [A0|A1] with per-col affine on A1 (BN fold);
//        2 split [A0|A1] with per-row LayerNorm fold (mean/rstd + gamma/beta).
// QKV:   gridDim.y selects B/bias/C from the three provided.
// ---------------------------------------------------------------------------
enum { EPI_GELU = 0, EPI_BIAS = 1, EPI_RES = 2 };
constexpr int SM_ALL = (128 * 128 + 2 * 4 * 8 * 32 * 4) * 4;   // 96 KB

template <int K, int EPI, int AMODE, bool BT, bool QKV>
__launch_bounds__(256, 2)
__global__ void gemm_k(const float* __restrict__ A0, const float* __restrict__ A1,
                       const float* __restrict__ B0, const float* __restrict__ B1,
                       const float* __restrict__ B2,
                       const float* __restrict__ bias0, const float* __restrict__ bias1,
                       const float* __restrict__ bias2,
                       const float* __restrict__ res,
                       const float* __restrict__ p0, const float* __restrict__ p1,
                       const float* __restrict__ p2, const float* __restrict__ p3,
                       float* __restrict__ C0, float* __restrict__ C1,
                       float* __restrict__ C2) {
    extern __shared__ float smem[];
    float2* Bs  = (float2*)smem;                       // 256 frags * 32 lanes
    float4* As4 = (float4*)(smem + 128 * 128);         // 2 bufs * 4 * 8 * 32

    const float* Bm = B0;
    const float* bias = bias0;
    float* Cm = C0;
    if (QKV) {
        int y = blockIdx.y;
        if (y == 1) { Bm = B1; bias = bias1; Cm = C1; }
        else if (y == 2) { Bm = B2; bias = bias2; Cm = C2; }
    }

    const int tid  = threadIdx.x;
    const int lane = tid & 31;
    const int wid  = tid >> 5;
    const int wm   = wid & 3;
    const int wn   = wid >> 2;
    const int row0 = blockIdx.x * 128;
    const int lr   = lane >> 2;
    const int lc   = lane & 3;

    const int r1 = row0 + wid * 16 + lr;
    const int r2 = r1 + 8;
    float m1 = 0.f, rs1 = 0.f, m2 = 0.f, rs2 = 0.f;
    if (AMODE == 2) { m1 = p0[r1]; rs1 = p1[r1]; m2 = p0[r2]; rs2 = p1[r2]; }

    auto fetch1 = [&](int r, float mn, float rsd, int c) -> float {
        if (AMODE == 0) return A0[(size_t)r * K + c];
        float v = (c < 128) ? A0[(size_t)r * 128 + c] : A1[(size_t)r * 128 + (c - 128)];
        if (AMODE == 1) { if (c >= 128) v = v * p0[c - 128] + p1[c - 128]; }
        else            { v = (v - mn) * rsd * p2[c] + p3[c]; }
        return v;
    };
    float4 pa[4];
    auto gather = [&](int kc) {
        #pragma unroll
        for (int i = 0; i < 4; i++) {
            int c = kc + i * 8 + lc;
            pa[i] = make_float4(tf32r(fetch1(r1, m1, rs1, c)),
                                tf32r(fetch1(r2, m2, rs2, c)),
                                tf32r(fetch1(r1, m1, rs1, c + 4)),
                                tf32r(fetch1(r2, m2, rs2, c + 4)));
        }
    };

    float acc[2][8][4] = {};
    gather(0);

    constexpr int NS = K / 32;
    #pragma unroll
    for (int s = 0; s < NS; s++) {
        if ((s & 3) == 0) {
            // load B chunk [ko, ko+128) in fragment order (conflict-free STS.64)
            const int ko = (s >> 2) * 128;
            for (int frag = wid; frag < 256; frag += 8) {
                int k8l = frag >> 4, nt = frag & 15;
                int kk = ko + k8l * 8 + lc, n = nt * 8 + lr;
                float b0v, b1v;
                if (BT) { b0v = Bm[(size_t)n * K + kk];   b1v = Bm[(size_t)n * K + kk + 4]; }
                else    { b0v = Bm[(size_t)kk * 128 + n]; b1v = Bm[(size_t)(kk + 4) * 128 + n]; }
                Bs[frag * 32 + lane] = make_float2(tf32r(b0v), tf32r(b1v));
            }
        }
        const int buf = s & 1;
        #pragma unroll
        for (int i = 0; i < 4; i++)
            As4[((buf * 4 + i) * 8 + wid) * 32 + lane] = pa[i];
        __syncthreads();
        if (s + 1 < NS) gather((s + 1) * 32);
        const int kb = (s & 3) * 4;
        #pragma unroll
        for (int k8 = 0; k8 < 4; k8++) {
            float4 a0 = As4[((buf * 4 + k8) * 8 + wm * 2 + 0) * 32 + lane];
            float4 a1 = As4[((buf * 4 + k8) * 8 + wm * 2 + 1) * 32 + lane];
            #pragma unroll
            for (int u = 0; u < 8; u++) {
                float2 b = Bs[((kb + k8) * 16 + wn * 8 + u) * 32 + lane];
                mma_tf32(acc[0][u], a0, b);
                mma_tf32(acc[1][u], a1, b);
            }
        }
        __syncthreads();
    }

    const int ec = lc * 2;
    #pragma unroll
    for (int t = 0; t < 2; t++) {
        int m0 = row0 + wm * 32 + t * 16 + lr;
        #pragma unroll
        for (int u = 0; u < 8; u++) {
            int n = wn * 64 + u * 8 + ec;
            float b0 = bias[n], b1 = bias[n + 1];
            float v0 = acc[t][u][0] + b0;
            float v1 = acc[t][u][1] + b1;
            float v2 = acc[t][u][2] + b0;
            float v3 = acc[t][u][3] + b1;
            if (EPI == EPI_GELU) {
                v0 = 0.5f * v0 * (1.0f + erff(v0 * 0.70710678f));
                v1 = 0.5f * v1 * (1.0f + erff(v1 * 0.70710678f));
                v2 = 0.5f * v2 * (1.0f + erff(v2 * 0.70710678f));
                v3 = 0.5f * v3 * (1.0f + erff(v3 * 0.70710678f));
            } else if (EPI == EPI_RES) {
                float2 r0 = *(const float2*)(res + (size_t)m0 * 128 + n);
                float2 rr = *(const float2*)(res + (size_t)(m0 + 8) * 128 + n);
                v0 += r0.x; v1 += r0.y; v2 += rr.x; v3 += rr.y;
            }
            *(float2*)(Cm + (size_t)m0 * 128 + n)       = make_float2(v0, v1);
            *(float2*)(Cm + (size_t)(m0 + 8) * 128 + n) = make_float2(v2, v3);
        }
    }
}

// ---------------------------------------------------------------------------
// LayerNorm stats only: per-token mean & rstd over the 256-wide concat
// ---------------------------------------------------------------------------
__global__ void ln_stats_k(const float* __restrict__ x1a, const float* __restrict__ x2a,
                           float* __restrict__ mean, float* __restrict__ rstd) {
    int warp = (blockIdx.x * blockDim.x + threadIdx.x) >> 5;
    int lane = threadIdx.x & 31;
    if (warp >= Mm) return;
    float s = 0.f, sq = 0.f;
    #pragma unroll
    for (int kq = 0; kq < 4; kq++) {
        float a = x1a[(size_t)warp * 128 + lane + 32 * kq];
        float b = x2a[(size_t)warp * 128 + lane + 32 * kq];
        s += a + b; sq += a * a + b * b;
    }
    #pragma unroll
    for (int o = 16; o > 0; o >>= 1) {
        s  += __shfl_xor_sync(0xffffffffu, s, o);
        sq += __shfl_xor_sync(0xffffffffu, sq, o);
    }
    if (lane == 0) {
        float mu = s * (1.f / 256.f);
        float var = sq * (1.f / 256.f) - mu * mu;
        mean[warp] = mu;
        rstd[warp] = rsqrtf(var + 1e-5f);
    }
}

// ---------------------------------------------------------------------------
// Window attention on tensor cores (validated in R5)
// ---------------------------------------------------------------------------
constexpr int QS_STRIDE = 132;
constexpr int VS_STRIDE = 136;
constexpr int PS_STRIDE = 68;
constexpr int ATTN_SMEM = (2 * 64 * QS_STRIDE + 64 * VS_STRIDE + 64 * PS_STRIDE) * 4;

__launch_bounds__(256)
__global__ void attn_k(const float* __restrict__ q, const float* __restrict__ k,
                       const float* __restrict__ v, float* __restrict__ out) {
    extern __shared__ float sm[];
    float* Qs = sm;
    float* Ks = Qs + 64 * QS_STRIDE;
    float* Vs = Ks + 64 * QS_STRIDE;
    float* Ps = Vs + 64 * VS_STRIDE;

    const int widx = blockIdx.x;
    const int b = widx >> 6, wh = (widx >> 3) & 7, ww = widx & 7;
    const int tid  = threadIdx.x;
    const int lane = tid & 31, w = tid >> 5;
    const int wm = w & 3, wn = w >> 2;
    const int lr = lane >> 2, lc = lane & 3;

    auto grow = [&](int i) -> size_t {
        return ((size_t)(b * Nn + (wh * 7 + i / 7) * 56 + ww * 7 + (i % 7))) * 128;
    };

    for (int e = tid; e < 49 * 32; e += 256) {
        int i = e >> 5, c4 = (e & 31) * 4;
        size_t g = grow(i) + c4;
        float4 a  = *(const float4*)(q + g);
        float4 kk = *(const float4*)(k + g);
        float4 vv = *(const float4*)(v + g);
        *(float4*)(Qs + i * QS_STRIDE + c4) =
            make_float4(tf32r(a.x), tf32r(a.y), tf32r(a.z), tf32r(a.w));
        *(float4*)(Ks + i * QS_STRIDE + c4) =
            make_float4(tf32r(kk.x), tf32r(kk.y), tf32r(kk.z), tf32r(kk.w));
        *(float4*)(Vs + i * VS_STRIDE + c4) =
            make_float4(tf32r(vv.x), tf32r(vv.y), tf32r(vv.z), tf32r(vv.w));
    }
    for (int e = tid; e < 15 * QS_STRIDE; e += 256) {
        Qs[49 * QS_STRIDE + e] = 0.f;
        Ks[49 * QS_STRIDE + e] = 0.f;
    }
    for (int e = tid; e < 15 * VS_STRIDE; e += 256) Vs[49 * VS_STRIDE + e] = 0.f;
    __syncthreads();

    float acc[4][4] = {};
    #pragma unroll
    for (int k8 = 0; k8 < 16; k8++) {
        int r = wm * 16 + lr, c = k8 * 8 + lc;
        float4 a = make_float4(Qs[r * QS_STRIDE + c],     Qs[(r + 8) * QS_STRIDE + c],
                               Qs[r * QS_STRIDE + c + 4], Qs[(r + 8) * QS_STRIDE + c + 4]);
        #pragma unroll
        for (int u = 0; u < 4; u++) {
            int n = wn * 32 + u * 8 + lr;
            float2 bf = make_float2(Ks[n * QS_STRIDE + c], Ks[n * QS_STRIDE + c + 4]);
            mma_tf32(acc[u], a, bf);
        }
    }
    #pragma unroll
    for (int u = 0; u < 4; u++) {
        int r = wm * 16 + lr, n = wn * 32 + u * 8 + lc * 2;
        *(float2*)(Ps + r * PS_STRIDE + n)       = make_float2(acc[u][0], acc[u][1]);
        *(float2*)(Ps + (r + 8) * PS_STRIDE + n) = make_float2(acc[u][2], acc[u][3]);
    }
    __syncthreads();

    if (tid < 49) {
        const float scale = 0.08838834764831845f;
        float* r = Ps + tid * PS_STRIDE;
        float mx = r[0];
        #pragma unroll 7
        for (int j = 1; j < 49; j++) mx = fmaxf(mx, r[j]);
        float s = 0.f;
        #pragma unroll 7
        for (int j = 0; j < 49; j++) { float e = expf((r[j] - mx) * scale); r[j] = e; s += e; }
        float inv = 1.f / s;
        #pragma unroll 7
        for (int j = 0; j < 49; j++) r[j] = tf32r(r[j] * inv);
        #pragma unroll
        for (int j = 49; j < 64; j++) r[j] = 0.f;
    }
    __syncthreads();

    float o[8][4] = {};
    #pragma unroll
    for (int k8 = 0; k8 < 8; k8++) {
        int r = wm * 16 + lr, c = k8 * 8 + lc;
        float4 a = make_float4(Ps[r * PS_STRIDE + c],     Ps[(r + 8) * PS_STRIDE + c],
                               Ps[r * PS_STRIDE + c + 4], Ps[(r + 8) * PS_STRIDE + c + 4]);
        #pragma unroll
        for (int u = 0; u < 8; u++) {
            int n = wn * 64 + u * 8 + lr;
            float2 bf = make_float2(Vs[c * VS_STRIDE + n], Vs[(c + 4) * VS_STRIDE + n]);
            mma_tf32(o[u], a, bf);
        }
    }
    int r0 = wm * 16 + lr;
    #pragma unroll
    for (int u = 0; u < 8; u++) {
        int n = wn * 64 + u * 8 + lc * 2;
        if (r0 < 49)     *(float2*)(out + grow(r0) + n)     = make_float2(o[u][0], o[u][1]);
        if (r0 + 8 < 49) *(float2*)(out + grow(r0 + 8) + n) = make_float2(o[u][2], o[u][3]);
    }
}

// ---------------------------------------------------------------------------
// BatchNorm pieces
// ---------------------------------------------------------------------------
__global__ void bn_stats_k(const float* __restrict__ x, float* __restrict__ part) {
    int c = threadIdx.x & 127;
    int half = threadIdx.x >> 7;
    float s = 0.f, sq = 0.f;
    int rbeg = blockIdx.x * 128 + half;
    int rend = blockIdx.x * 128 + 128;
    for (int r = rbeg; r < rend; r += 2) {
        float vv = x[(size_t)r * 128 + c];
        s += vv; sq += vv * vv;
    }
    __shared__ float sh[512];
    sh[threadIdx.x] = s;
    sh[256 + threadIdx.x] = sq;
    __syncthreads();
    if (half == 0) {
        part[blockIdx.x * 256 + c]       = sh[c] + sh[128 + c];
        part[blockIdx.x * 256 + 128 + c] = sh[256 + c] + sh[256 + 128 + c];
    }
}

__global__ void bn_apply_relu_stats_k(float* __restrict__ x,
                                      const float* __restrict__ scale,
                                      const float* __restrict__ shift,
                                      float* __restrict__ part) {
    int c = threadIdx.x & 127;
    int half = threadIdx.x >> 7;
    float sc = scale[c], sh_ = shift[c];
    float s = 0.f, sq = 0.f;
    int rbeg = blockIdx.x * 128 + half;
    int rend = blockIdx.x * 128 + 128;
    for (int r = rbeg; r < rend; r += 2) {
        float vv = fmaxf(x[(size_t)r * 128 + c] * sc + sh_, 0.f);
        x[(size_t)r * 128 + c] = vv;
        s += vv; sq += vv * vv;
    }
    __shared__ float shm[512];
    shm[threadIdx.x] = s;
    shm[256 + threadIdx.x] = sq;
    __syncthreads();
    if (half == 0) {
        part[blockIdx.x * 256 + c]       = shm[c] + shm[128 + c];
        part[blockIdx.x * 256 + 128 + c] = shm[256 + c] + shm[256 + 128 + c];
    }
}

__global__ void bn_reduce_k(const float* __restrict__ part, const float* __restrict__ g,
                            const float* __restrict__ beta, float* __restrict__ scale,
                            float* __restrict__ shift) {
    int c = threadIdx.x;
    float s = 0.f, sq = 0.f;
    for (int i = 0; i < 784; i++) {
        s  += part[i * 256 + c];
        sq += part[i * 256 + 128 + c];
    }
    float mean = s / (float)Mm;
    float var  = sq / (float)Mm - mean * mean;
    float sc_  = g[c] * rsqrtf(var + 1e-5f);
    scale[c] = sc_;
    shift[c] = beta[c] - mean * sc_;
}

// ---------------------------------------------------------------------------
// Host launch
// ---------------------------------------------------------------------------
static float* symaddr(const void* devsym) {
    void* p = nullptr;
    cudaGetSymbolAddress(&p, devsym);
    return (float*)p;
}

extern "C" void kernel_launch(void* const* d_in, const int* in_sizes, int n_in,
                              void* d_out, int out_size) {
    const float* x     = (const float*)d_in[0];
    const float* fc1_w = (const float*)d_in[1];
    const float* fc1_b = (const float*)d_in[2];
    const float* fc2_w = (const float*)d_in[3];
    const float* fc2_b = (const float*)d_in[4];
    const float* fc3_w = (const float*)d_in[5];
    const float* fc3_b = (const float*)d_in[6];
    const float* fc4_w = (const float*)d_in[7];
    const float* fc4_b = (const float*)d_in[8];
    const float* fc5_w = (const float*)d_in[9];
    const float* fc5_b = (const float*)d_in[10];
    const float* fc6_w = (const float*)d_in[11];
    const float* fc6_b = (const float*)d_in[12];
    const float* ln_w  = (const float*)d_in[13];
    const float* ln_b  = (const float*)d_in[14];
    const float* q_w   = (const float*)d_in[15];
    const float* q_b   = (const float*)d_in[16];
    const float* k_w   = (const float*)d_in[17];
    const float* k_b   = (const float*)d_in[18];
    const float* v_w   = (const float*)d_in[19];
    const float* v_b   = (const float*)d_in[20];
    const float* bn1_g = (const float*)d_in[21];
    const float* bn1_b = (const float*)d_in[22];
    const float* bn2_g = (const float*)d_in[23];
    const float* bn2_b = (const float*)d_in[24];

    float* t0   = symaddr(g_t0);
    float* t1   = symaddr(g_t1);
    float* x1a  = symaddr(g_x1a);
    float* x2a  = symaddr(g_x2a);
    float* qb   = symaddr(g_q);
    float* kb   = symaddr(g_k);
    float* vb   = symaddr(g_v);
    float* att  = symaddr(g_att);
    float* stat = symaddr(g_stats);
    float* mean = stat;
    float* rstd = stat + Mm;
    float* part = symaddr(g_part);
    float* scl  = symaddr(g_scale);
    float* shf  = symaddr(g_shift);

    const int gridR = Bb * 56;
    const int gridG = Mm / 128;          // 784

    auto setsm = [](const void* f) {
        cudaFuncSetAttribute(f, cudaFuncAttributeMaxDynamicSharedMemorySize, SM_ALL);
    };
    setsm((const void*)gemm_k<128, EPI_GELU, 0, false, false>);
    setsm((const void*)gemm_k<128, EPI_RES,  0, false, false>);
    setsm((const void*)gemm_k<128, EPI_BIAS, 0, true,  true >);
    setsm((const void*)gemm_k<256, EPI_RES,  2, false, false>);
    setsm((const void*)gemm_k<256, EPI_BIAS, 1, false, false>);
    cudaFuncSetAttribute(attn_k, cudaFuncAttributeMaxDynamicSharedMemorySize, ATTN_SMEM);

    #define GEMM_ARGS(A0,A1,B,bias,res,q0,q1,q2,q3,C) \
        A0, A1, B, nullptr, nullptr, bias, nullptr, nullptr, res, q0, q1, q2, q3, C, nullptr, nullptr

    // Branch 1
    roll_k<0><<<gridR, 256>>>(x, t0);
    gemm_k<128, EPI_GELU, 0, false, false><<<gridG, 256, SM_ALL>>>(
        GEMM_ARGS(t0, nullptr, fc1_w, fc1_b, nullptr, nullptr, nullptr, nullptr, nullptr, t1));
    roll_k<1><<<gridR, 256>>>(t1, t0);
    gemm_k<128, EPI_RES, 0, false, false><<<gridG, 256, SM_ALL>>>(
        GEMM_ARGS(t0, nullptr, fc2_w, fc2_b, x, nullptr, nullptr, nullptr, nullptr, x1a));

    // Branch 2
    roll_k<2><<<gridR, 256>>>(x, t0);
    gemm_k<128, EPI_GELU, 0, false, false><<<gridG, 256, SM_ALL>>>(
        GEMM_ARGS(t0, nullptr, fc3_w, fc3_b, nullptr, nullptr, nullptr, nullptr, nullptr, t1));
    roll_k<0><<<gridR, 256>>>(t1, t0);
    gemm_k<128, EPI_RES, 0, false, false><<<gridG, 256, SM_ALL>>>(
        GEMM_ARGS(t0, nullptr, fc4_w, fc4_b, x, nullptr, nullptr, nullptr, nullptr, x2a));

    // LN stats + fc5 (LN folded into A-gather) + residual -> t0
    ln_stats_k<<<Mm / 8, 256>>>(x1a, x2a, mean, rstd);
    gemm_k<256, EPI_RES, 2, false, false><<<gridG, 256, SM_ALL>>>(
        x1a, x2a, fc5_w, nullptr, nullptr, fc5_b, nullptr, nullptr, x,
        mean, rstd, ln_w, ln_b, t0, nullptr, nullptr);

    // q/k/v in one launch (grid.y selects weight/bias/output)
    gemm_k<128, EPI_BIAS, 0, true, true><<<dim3(gridG, 3), 256, SM_ALL>>>(
        x, nullptr, q_w, k_w, v_w, q_b, k_b, v_b, nullptr,
        nullptr, nullptr, nullptr, nullptr, qb, kb, vb);

    // Window attention (tensor cores)
    attn_k<<<2048, 256, ATTN_SMEM>>>(qb, kb, vb, att);

    // BN1 -> (apply+ReLU, BN2 stats) -> BN2 folded into fc6 A-load
    bn_stats_k<<<784, 256>>>(att, part);
    bn_reduce_k<<<1, 128>>>(part, bn1_g, bn1_b, scl, shf);
    bn_apply_relu_stats_k<<<784, 256>>>(att, scl, shf, part);
    bn_reduce_k<<<1, 128>>>(part, bn2_g, bn2_b, scl, shf);

    // Final: out = [x1 | BN2(att)] @ fc6 + b
    gemm_k<256, EPI_BIAS, 1, false, false><<<gridG, 256, SM_ALL>>>(
        t0, att, fc6_w, nullptr, nullptr, fc6_b, nullptr, nullptr, nullptr,
        scl, shf, nullptr, nullptr, (float*)d_out, nullptr, nullptr);
}